// round 9
// baseline (speedup 1.0000x reference)
#include <cuda_runtime.h>
#include <math.h>
#include <float.h>

#define QLEN 1024
#define DMODEL 4096
#define NH 32
#define NKV 8
#define HD 128
#define OUTL 16
#define KEEP 256

// ---------------- scratch (static device globals; no allocation) ----------------
__device__ float g_qlin[QLEN * DMODEL];
__device__ float g_klin[QLEN * NKV * HD];
__device__ float g_vlin[QLEN * NKV * HD];
__device__ float g_qr[NH * QLEN * HD];
__device__ float g_kr[NKV * QLEN * HD];
__device__ float g_vr[NKV * QLEN * HD];
__device__ float g_gq[NH * QLEN * OUTL];
__device__ float g_gk[NH * QLEN * OUTL];
__device__ float g_o[QLEN * NH * HD];

// ---------------- 3xTF32 tensor-core GEMM, packed LDS.128 fragments -------------
// smem element (row r, k): uint4 (hi_k, lo_k, hi_{k+4}, lo_{k+4}) at
// [r][(k>>3)*4 + (k&3)] -- one LDS.128 yields a full (hi,lo)x(k,k+4) fragment.
// Values and MMA order identical to rounds 7/8 -> bit-identical results.
#define GBM 128
#define GBN 64
#define GBK 32
#define KP2 (GBK / 2 + 1)     // 16 pairs + 1 pad (uint4 units)

__device__ __forceinline__ void tf32_split(float x, unsigned& hi, unsigned& lo) {
    unsigned h;
    asm("cvt.rna.tf32.f32 %0, %1;" : "=r"(h) : "f"(x));
    float r = __fadd_rn(x, -__uint_as_float(h));
    unsigned l;
    asm("cvt.rna.tf32.f32 %0, %1;" : "=r"(l) : "f"(r));
    hi = h; lo = l;
}

__device__ __forceinline__ void mma_tf32(float* d, const unsigned* a, const unsigned* b) {
    asm volatile(
        "mma.sync.aligned.m16n8k8.row.col.f32.tf32.tf32.f32 "
        "{%0,%1,%2,%3}, {%4,%5,%6,%7}, {%8,%9}, {%0,%1,%2,%3};"
        : "+f"(d[0]), "+f"(d[1]), "+f"(d[2]), "+f"(d[3])
        : "r"(a[0]), "r"(a[1]), "r"(a[2]), "r"(a[3]), "r"(b[0]), "r"(b[1]));
}

__global__ __launch_bounds__(256) void gemm_tf32(
    const float* __restrict__ A,
    const float* __restrict__ B0, float* __restrict__ C0,
    const float* __restrict__ B1, float* __restrict__ C1,
    int N, int K)
{
    const float* B = (blockIdx.z == 0) ? B0 : B1;
    float* C = (blockIdx.z == 0) ? C0 : C1;

    __shared__ uint4 As[GBM][KP2];   // ~34.8 KB
    __shared__ uint4 Bs[GBN][KP2];   // ~17.4 KB

    int tid = threadIdx.x;
    int lane = tid & 31;
    int wid = tid >> 5;
    int wm = (wid >> 1) * 32;
    int wn = (wid & 1) * 32;
    int g = lane >> 2;
    int t4 = lane & 3;

    int bm = blockIdx.y * GBM;
    int bn = blockIdx.x * GBN;

    int arow[4], acol[4];
#pragma unroll
    for (int i = 0; i < 4; ++i) {
        int idx = tid + i * 256;
        arow[i] = idx >> 3;
        acol[i] = (idx & 7) << 2;
    }
    int bkrow[2], bncol[2];
#pragma unroll
    for (int i = 0; i < 2; ++i) {
        int idx = tid + i * 256;
        bkrow[i] = idx >> 4;
        bncol[i] = (idx & 15) << 2;
    }

    float acc[2][4][4], mst[2][4][4];
#pragma unroll
    for (int mt = 0; mt < 2; ++mt)
#pragma unroll
        for (int nt = 0; nt < 4; ++nt)
#pragma unroll
            for (int r = 0; r < 4; ++r) { acc[mt][nt][r] = 0.f; mst[mt][nt][r] = 0.f; }

    float4 ra[4], rb[2];
#pragma unroll
    for (int i = 0; i < 4; ++i)
        ra[i] = *(const float4*)&A[(size_t)(bm + arow[i]) * K + acol[i]];
#pragma unroll
    for (int i = 0; i < 2; ++i)
        rb[i] = *(const float4*)&B[(size_t)bkrow[i] * N + bn + bncol[i]];

    int ntiles = K / GBK;
    for (int t = 0; t < ntiles; ++t) {
        // split + packed store: A cols c..c+3 (c % 4 == 0) -> pairs (c>>3)*4+q, slot (c&4)>>2
#pragma unroll
        for (int i = 0; i < 4; ++i) {
            int r = arow[i], c = acol[i];
            int pbase = (c >> 3) * 4 + (c & 3);
            int slot2 = ((c & 4) >> 2) * 2;
            unsigned* base = (unsigned*)&As[r][pbase];
            const float* vv = (const float*)&ra[i];
#pragma unroll
            for (int q = 0; q < 4; ++q) {
                unsigned h, l;
                tf32_split(vv[q], h, l);
                base[q * 4 + slot2] = h;
                base[q * 4 + slot2 + 1] = l;
            }
        }
#pragma unroll
        for (int i = 0; i < 2; ++i) {
            int k = bkrow[i], n4 = bncol[i];
            int pair = (k >> 3) * 4 + (k & 3);
            int slot2 = ((k & 4) >> 2) * 2;
            const float* vv = (const float*)&rb[i];
#pragma unroll
            for (int q = 0; q < 4; ++q) {
                unsigned h, l;
                tf32_split(vv[q], h, l);
                unsigned* base = (unsigned*)&Bs[n4 + q][pair];
                base[slot2] = h;
                base[slot2 + 1] = l;
            }
        }
        __syncthreads();

        if (t + 1 < ntiles) {
            int k0 = (t + 1) * GBK;
#pragma unroll
            for (int i = 0; i < 4; ++i)
                ra[i] = *(const float4*)&A[(size_t)(bm + arow[i]) * K + k0 + acol[i]];
#pragma unroll
            for (int i = 0; i < 2; ++i)
                rb[i] = *(const float4*)&B[(size_t)(k0 + bkrow[i]) * N + bn + bncol[i]];
        }

#pragma unroll
        for (int ks = 0; ks < GBK / 8; ++ks) {
            int pidx = ks * 4 + t4;
            unsigned ah[2][4], al[2][4];
#pragma unroll
            for (int mt = 0; mt < 2; ++mt) {
                int r0 = wm + mt * 16;
                uint4 v0 = As[r0 + g][pidx];
                uint4 v1 = As[r0 + g + 8][pidx];
                ah[mt][0] = v0.x; al[mt][0] = v0.y;
                ah[mt][2] = v0.z; al[mt][2] = v0.w;
                ah[mt][1] = v1.x; al[mt][1] = v1.y;
                ah[mt][3] = v1.z; al[mt][3] = v1.w;
            }
            unsigned bh[4][2], bl[4][2];
#pragma unroll
            for (int nt = 0; nt < 4; ++nt) {
                uint4 v = Bs[wn + nt * 8 + g][pidx];
                bh[nt][0] = v.x; bl[nt][0] = v.y;
                bh[nt][1] = v.z; bl[nt][1] = v.w;
            }
#pragma unroll
            for (int mt = 0; mt < 2; ++mt)
#pragma unroll
                for (int nt = 0; nt < 4; ++nt) {
                    mma_tf32(acc[mt][nt], ah[mt], bh[nt]);
                    mma_tf32(acc[mt][nt], al[mt], bh[nt]);
                    mma_tf32(acc[mt][nt], ah[mt], bl[nt]);
                }
        }
        __syncthreads();

        if ((t & 3) == 3) {
#pragma unroll
            for (int mt = 0; mt < 2; ++mt)
#pragma unroll
                for (int nt = 0; nt < 4; ++nt)
#pragma unroll
                    for (int r = 0; r < 4; ++r) {
                        mst[mt][nt][r] = __fadd_rn(mst[mt][nt][r], acc[mt][nt][r]);
                        acc[mt][nt][r] = 0.f;
                    }
        }
    }

#pragma unroll
    for (int mt = 0; mt < 2; ++mt)
#pragma unroll
        for (int nt = 0; nt < 4; ++nt) {
            int r0 = bm + wm + mt * 16 + g;
            int c0 = bn + wn + nt * 8 + t4 * 2;
            *(float2*)&C[(size_t)r0 * N + c0] =
                make_float2(mst[mt][nt][0], mst[mt][nt][1]);
            *(float2*)&C[(size_t)(r0 + 8) * N + c0] =
                make_float2(mst[mt][nt][2], mst[mt][nt][3]);
        }
}

// ---------------- RoPE + layout transpose (precision-matched) ----------------
__global__ void rope_kernel()
{
    int p = blockIdx.x;
    int hh = blockIdx.y;
    int d = threadIdx.x;

    int i = d & 63;
    float P = (float)pow(10000.0, (double)(2 * i) / 128.0);
    float invf = __fdiv_rn(1.0f, P);
    float ang = __fmul_rn((float)p, invf);
    float c = (float)cos((double)ang);
    float s = (float)sin((double)ang);

    if (hh < NH) {
        const float* base = &g_qlin[(size_t)p * DMODEL + hh * HD];
        float v = base[d];
        float other = (d < 64) ? -base[d + 64] : base[d - 64];
        g_qr[((size_t)hh * QLEN + p) * HD + d] =
            __fadd_rn(__fmul_rn(v, c), __fmul_rn(other, s));
    } else if (hh < NH + NKV) {
        int kvh = hh - NH;
        const float* base = &g_klin[(size_t)p * (NKV * HD) + kvh * HD];
        float v = base[d];
        float other = (d < 64) ? -base[d + 64] : base[d - 64];
        g_kr[((size_t)kvh * QLEN + p) * HD + d] =
            __fadd_rn(__fmul_rn(v, c), __fmul_rn(other, s));
    } else {
        int kvh = hh - NH - NKV;
        g_vr[((size_t)kvh * QLEN + p) * HD + d] =
            g_vlin[(size_t)p * (NKV * HD) + kvh * HD + d];
    }
}

// ---------------- label build: 8 warps per block, one (p,h) per warp ------------
__global__ __launch_bounds__(256) void gqk_kernel(const int* __restrict__ sorted_channel)
{
    int warp = threadIdx.x >> 5;
    int lane = threadIdx.x & 31;
    int p = blockIdx.x;
    int h = blockIdx.y * 8 + warp;

    int j = lane & 15;
    bool isK = lane >= 16;

    int ch = sorted_channel[h * HD + j];
    float t;
    if (!isK) t = g_qr[((size_t)h * QLEN + p) * HD + ch];
    else      t = g_kr[((size_t)(h >> 2) * QLEN + p) * HD + ch];

    float mn = t, mx = t;
#pragma unroll
    for (int off = 1; off < 16; off <<= 1) {
        mn = fminf(mn, __shfl_xor_sync(0xffffffffu, mn, off));
        mx = fmaxf(mx, __shfl_xor_sync(0xffffffffu, mx, off));
    }
    float rng = __fadd_rn(mx, -mn);
    if (rng == 0.0f) rng = 1.0f;
    float scale = __fdiv_rn(15.0f, rng);
    float qv = rintf(__fmul_rn(__fadd_rn(t, -mn), scale));
    qv = fminf(fmaxf(qv, 0.0f), 15.0f);
    float outv = __fadd_rn(__fdiv_rn(qv, scale), mn);

    if (!isK) g_gq[((size_t)h * QLEN + p) * OUTL + j] = outv;
    else      g_gk[((size_t)h * QLEN + p) * OUTL + j] = outv;
}

// ---------------- fused gattn -> stable top-256 -> attn -> softmax -> AV ----
__global__ __launch_bounds__(256) void attn_kernel()
{
    int p = blockIdx.x;
    int h = blockIdx.y;
    int kvh = h >> 2;
    int tid = threadIdx.x;
    int lane = tid & 31;
    int warp = tid >> 5;
    unsigned lmask = (1u << lane) - 1u;

    __shared__ float gq_s[OUTL];
    __shared__ float q_s[HD];
    __shared__ unsigned keys[QLEN];
    __shared__ unsigned hist[256];
    __shared__ unsigned wsum[8];
    __shared__ int kept_idx[KEEP];
    __shared__ float attw[KEEP];
    __shared__ float obuf[HD];
    __shared__ unsigned sh_prefix;
    __shared__ int sh_want;
    __shared__ int wcnt[8];
    __shared__ int wcnt2[8];
    __shared__ int eqbase_s;
    __shared__ int kbase_s;
    __shared__ float red[8];
    __shared__ float sh_scalar;

    if (tid < OUTL) gq_s[tid] = g_gq[((size_t)h * QLEN + p) * OUTL + tid];
    if (tid < HD)   q_s[tid] = g_qr[((size_t)h * QLEN + p) * HD + tid];
    if (tid == 0) { eqbase_s = 0; kbase_s = 0; }
    __syncthreads();

    int nvalid = p + 1;

    // 1. gattn keys: strict ascending sequential FMA chain, exact /4.
    for (int j = tid; j < nvalid; j += 256) {
        const float* g = &g_gk[((size_t)h * QLEN + j) * OUTL];
        float s = __fmul_rn(g[0], gq_s[0]);
#pragma unroll
        for (int d = 1; d < OUTL; ++d)
            s = __fmaf_rn(g[d], gq_s[d], s);
        s = __fmul_rn(s, 0.25f);
        unsigned u = __float_as_uint(s);
        if ((u << 1) == 0u) u = 0u;
        u ^= (u & 0x80000000u) ? 0xFFFFFFFFu : 0x80000000u;
        keys[j] = u;
    }
    __syncthreads();

    // 2. stable top-KEEP selection (radix threshold + ordered compaction)
    int cnt;
    if (nvalid <= KEEP) {
        for (int j = tid; j < nvalid; j += 256) kept_idx[j] = j;
        cnt = nvalid;
        __syncthreads();
    } else {
        unsigned prefix = 0;
        int want = KEEP;
        for (int byte = 3; byte >= 0; --byte) {
            hist[tid] = 0;
            __syncthreads();
            int shift = byte * 8;
            unsigned pmask = (byte == 3) ? 0u : (0xFFFFFFFFu << (shift + 8));
            for (int j = tid; j < nvalid; j += 256) {
                unsigned u = keys[j];
                if ((u & pmask) == prefix)
                    atomicAdd(&hist[(u >> shift) & 255u], 1u);
            }
            __syncthreads();

            unsigned hv = hist[tid];
            unsigned s = hv;
#pragma unroll
            for (int off = 1; off < 32; off <<= 1) {
                unsigned t2 = __shfl_down_sync(0xffffffffu, s, off);
                if (lane + off < 32) s += t2;
            }
            if (lane == 0) wsum[warp] = s;
            __syncthreads();
            unsigned add = 0;
#pragma unroll
            for (int w = 0; w < 8; ++w)
                if (w > warp) add += wsum[w];
            unsigned suft = s + add;
            unsigned above = suft - hv;
            if (suft >= (unsigned)want && above < (unsigned)want) {
                sh_prefix = prefix | ((unsigned)tid << shift);
                sh_want = want - (int)above;
            }
            __syncthreads();
            prefix = sh_prefix;
            want = sh_want;
            __syncthreads();
        }
        unsigned uT = prefix;
        int r = want;

        // ordered stable compaction: chunks in order, lanes in order -> ascending
#pragma unroll
        for (int chunk = 0; chunk < QLEN / 256; ++chunk) {
            int j = chunk * 256 + tid;
            bool isval = j < nvalid;
            unsigned u = isval ? keys[j] : 0u;
            bool gt = isval && (u > uT);
            bool eq = isval && (u == uT);

            unsigned bal_eq = __ballot_sync(0xffffffffu, eq);
            if (lane == 0) wcnt[warp] = __popc(bal_eq);
            __syncthreads();
            int eqoff = eqbase_s;
            for (int w = 0; w < warp; ++w) eqoff += wcnt[w];
            int eqrank = eqoff + __popc(bal_eq & lmask);
            bool keep = gt || (eq && eqrank < r);

            unsigned bal_k = __ballot_sync(0xffffffffu, keep);
            if (lane == 0) wcnt2[warp] = __popc(bal_k);
            __syncthreads();
            int koff = kbase_s;
            for (int w = 0; w < warp; ++w) koff += wcnt2[w];
            if (keep) kept_idx[koff + __popc(bal_k & lmask)] = j;
            __syncthreads();
            if (tid == 0) {
                int te = 0, tk = 0;
                for (int w = 0; w < 8; ++w) { te += wcnt[w]; tk += wcnt2[w]; }
                eqbase_s += te;
                kbase_s += tk;
            }
            __syncthreads();
        }
        cnt = kbase_s;
    }
    __syncthreads();

    // 3. attn scores on kept columns (warp per column, float4 loads)
    {
        float4 qreg = *(const float4*)&q_s[lane * 4];
        for (int c = warp; c < cnt; c += 8) {
            int j = kept_idx[c];
            float4 kv = *(const float4*)&g_kr[((size_t)kvh * QLEN + j) * HD + lane * 4];
            float s = __fmul_rn(qreg.x, kv.x);
            s = __fmaf_rn(qreg.y, kv.y, s);
            s = __fmaf_rn(qreg.z, kv.z, s);
            s = __fmaf_rn(qreg.w, kv.w, s);
#pragma unroll
            for (int off = 16; off; off >>= 1) s += __shfl_xor_sync(0xffffffffu, s, off);
            if (lane == 0) attw[c] = s / 11.313708498984761f;
        }
    }
    __syncthreads();

    // 4. softmax over kept (exp via double -> correctly rounded fp32)
    float vmax = -FLT_MAX;
    for (int c = tid; c < cnt; c += 256) vmax = fmaxf(vmax, attw[c]);
#pragma unroll
    for (int off = 16; off; off >>= 1)
        vmax = fmaxf(vmax, __shfl_xor_sync(0xffffffffu, vmax, off));
    if (lane == 0) red[warp] = vmax;
    __syncthreads();
    if (warp == 0) {
        float m = (lane < 8) ? red[lane] : -FLT_MAX;
#pragma unroll
        for (int off = 4; off; off >>= 1)
            m = fmaxf(m, __shfl_xor_sync(0xffffffffu, m, off));
        if (lane == 0) sh_scalar = m;
    }
    __syncthreads();
    float M = sh_scalar;

    float lsum = 0.f;
    for (int c = tid; c < cnt; c += 256) {
        float e = (float)exp((double)__fadd_rn(attw[c], -M));
        attw[c] = e;
        lsum += e;
    }
#pragma unroll
    for (int off = 16; off; off >>= 1)
        lsum += __shfl_xor_sync(0xffffffffu, lsum, off);
    if (lane == 0) red[warp] = lsum;
    __syncthreads();
    if (warp == 0) {
        float s2 = (lane < 8) ? red[lane] : 0.f;
#pragma unroll
        for (int off = 4; off; off >>= 1)
            s2 += __shfl_xor_sync(0xffffffffu, s2, off);
        if (lane == 0) sh_scalar = s2;
    }
    __syncthreads();
    float denom = sh_scalar;

    for (int c = tid; c < cnt; c += 256)
        attw[c] = __fdiv_rn(attw[c], denom);
    __syncthreads();

    // 5. AV: two halves of the block split the kept columns
    {
        int d = tid & 127;
        int half = tid >> 7;
        float acc = 0.f;
        const float* vbase = &g_vr[(size_t)kvh * QLEN * HD + d];
        for (int c = half; c < cnt; c += 2)
            acc = __fmaf_rn(attw[c], __ldg(&vbase[(size_t)kept_idx[c] * HD]), acc);
        if (half == 0) obuf[d] = acc;
        __syncthreads();
        if (half == 1)
            g_o[(size_t)p * (NH * HD) + h * HD + d] = __fadd_rn(obuf[d], acc);
    }
}

// ---------------- launch ----------------
extern "C" void kernel_launch(void* const* d_in, const int* in_sizes, int n_in,
                              void* d_out, int out_size)
{
    const float* hidden = (const float*)d_in[0];
    const float* Wq = (const float*)d_in[3];
    const float* Wk = (const float*)d_in[4];
    const float* Wv = (const float*)d_in[5];
    const float* Wo = (const float*)d_in[6];
    const int* sorted_channel = (const int*)d_in[7];
    float* out = (float*)d_out;

    float *qlin, *klin, *vlin, *o;
    cudaGetSymbolAddress((void**)&qlin, g_qlin);
    cudaGetSymbolAddress((void**)&klin, g_klin);
    cudaGetSymbolAddress((void**)&vlin, g_vlin);
    cudaGetSymbolAddress((void**)&o, g_o);

    dim3 t256(256);
    gemm_tf32<<<dim3(DMODEL / GBN, QLEN / GBM, 1), t256>>>(
        hidden, Wq, qlin, Wq, qlin, DMODEL, DMODEL);
    gemm_tf32<<<dim3((NKV * HD) / GBN, QLEN / GBM, 2), t256>>>(
        hidden, Wk, klin, Wv, vlin, NKV * HD, DMODEL);
    rope_kernel<<<dim3(QLEN, NH + 2 * NKV), 128>>>();
    gqk_kernel<<<dim3(QLEN, NH / 8), t256>>>(sorted_channel);
    attn_kernel<<<dim3(QLEN, NH), t256>>>();
    gemm_tf32<<<dim3(DMODEL / GBN, QLEN / GBM, 1), t256>>>(
        o, Wo, out, Wo, out, DMODEL, DMODEL);
}

// round 10
// speedup vs baseline: 1.1381x; 1.1381x over previous
#include <cuda_runtime.h>
#include <math.h>
#include <float.h>

#define QLEN 1024
#define DMODEL 4096
#define NH 32
#define NKV 8
#define HD 128
#define OUTL 16
#define KEEP 256

// ---------------- scratch (static device globals; no allocation) ----------------
__device__ float g_qlin[QLEN * DMODEL];
__device__ float g_klin[QLEN * NKV * HD];
__device__ float g_vlin[QLEN * NKV * HD];
__device__ float g_qr[NH * QLEN * HD];
__device__ float g_kr[NKV * QLEN * HD];
__device__ float g_vr[NKV * QLEN * HD];
__device__ float g_gq[NH * QLEN * OUTL];
__device__ float g_gk[NH * QLEN * OUTL];
__device__ float g_o[QLEN * NH * HD];

// ---------------- 3xTF32 tensor-core GEMM (round-7 form: best measured) ---------
#define GBM 128
#define GBN 64
#define GBK 32
#define SPITCH (GBK + 4)

__device__ __forceinline__ void tf32_split(float x, unsigned& hi, unsigned& lo) {
    unsigned h;
    asm("cvt.rna.tf32.f32 %0, %1;" : "=r"(h) : "f"(x));
    float r = __fadd_rn(x, -__uint_as_float(h));
    unsigned l;
    asm("cvt.rna.tf32.f32 %0, %1;" : "=r"(l) : "f"(r));
    hi = h; lo = l;
}

__device__ __forceinline__ void mma_tf32(float* d, const unsigned* a, const unsigned* b) {
    asm volatile(
        "mma.sync.aligned.m16n8k8.row.col.f32.tf32.tf32.f32 "
        "{%0,%1,%2,%3}, {%4,%5,%6,%7}, {%8,%9}, {%0,%1,%2,%3};"
        : "+f"(d[0]), "+f"(d[1]), "+f"(d[2]), "+f"(d[3])
        : "r"(a[0]), "r"(a[1]), "r"(a[2]), "r"(a[3]), "r"(b[0]), "r"(b[1]));
}

__global__ __launch_bounds__(256) void gemm_tf32(
    const float* __restrict__ A,
    const float* __restrict__ B0, float* __restrict__ C0,
    const float* __restrict__ B1, float* __restrict__ C1,
    int N, int K)
{
    const float* B = (blockIdx.z == 0) ? B0 : B1;
    float* C = (blockIdx.z == 0) ? C0 : C1;

    __shared__ float As[GBM][SPITCH];
    __shared__ float Bs[GBN][SPITCH];

    int tid = threadIdx.x;
    int lane = tid & 31;
    int wid = tid >> 5;
    int wm = (wid >> 1) * 32;
    int wn = (wid & 1) * 32;
    int g = lane >> 2;
    int t4 = lane & 3;

    int bm = blockIdx.y * GBM;
    int bn = blockIdx.x * GBN;

    float acc[2][4][4];
    float mst[2][4][4];
#pragma unroll
    for (int mt = 0; mt < 2; ++mt)
#pragma unroll
        for (int nt = 0; nt < 4; ++nt)
#pragma unroll
            for (int r = 0; r < 4; ++r) { acc[mt][nt][r] = 0.f; mst[mt][nt][r] = 0.f; }

    int ntiles = K / GBK;
    for (int t = 0; t < ntiles; ++t) {
        int k0 = t * GBK;
#pragma unroll
        for (int i = 0; i < 4; ++i) {
            int idx = tid + i * 256;
            int r = idx >> 3;
            int c = (idx & 7) << 2;
            float4 v = *(const float4*)&A[(size_t)(bm + r) * K + k0 + c];
            *(float4*)&As[r][c] = v;
        }
#pragma unroll
        for (int i = 0; i < 2; ++i) {
            int idx = tid + i * 256;
            int k = idx >> 4;
            int n4 = (idx & 15) << 2;
            float4 v = *(const float4*)&B[(size_t)(k0 + k) * N + bn + n4];
            Bs[n4 + 0][k] = v.x;
            Bs[n4 + 1][k] = v.y;
            Bs[n4 + 2][k] = v.z;
            Bs[n4 + 3][k] = v.w;
        }
        __syncthreads();

#pragma unroll
        for (int ks = 0; ks < GBK / 8; ++ks) {
            int kb = ks * 8;
            unsigned ah[2][4], al[2][4];
#pragma unroll
            for (int mt = 0; mt < 2; ++mt) {
                int r0 = wm + mt * 16;
                tf32_split(As[r0 + g][kb + t4],          ah[mt][0], al[mt][0]);
                tf32_split(As[r0 + g + 8][kb + t4],      ah[mt][1], al[mt][1]);
                tf32_split(As[r0 + g][kb + t4 + 4],      ah[mt][2], al[mt][2]);
                tf32_split(As[r0 + g + 8][kb + t4 + 4],  ah[mt][3], al[mt][3]);
            }
            unsigned bh[4][2], bl[4][2];
#pragma unroll
            for (int nt = 0; nt < 4; ++nt) {
                int col = wn + nt * 8 + g;
                tf32_split(Bs[col][kb + t4],     bh[nt][0], bl[nt][0]);
                tf32_split(Bs[col][kb + t4 + 4], bh[nt][1], bl[nt][1]);
            }
#pragma unroll
            for (int mt = 0; mt < 2; ++mt)
#pragma unroll
                for (int nt = 0; nt < 4; ++nt) {
                    mma_tf32(acc[mt][nt], ah[mt], bh[nt]);
                    mma_tf32(acc[mt][nt], al[mt], bh[nt]);
                    mma_tf32(acc[mt][nt], ah[mt], bl[nt]);
                }
        }
        __syncthreads();

        if ((t & 3) == 3) {
#pragma unroll
            for (int mt = 0; mt < 2; ++mt)
#pragma unroll
                for (int nt = 0; nt < 4; ++nt)
#pragma unroll
                    for (int r = 0; r < 4; ++r) {
                        mst[mt][nt][r] = __fadd_rn(mst[mt][nt][r], acc[mt][nt][r]);
                        acc[mt][nt][r] = 0.f;
                    }
        }
    }

#pragma unroll
    for (int mt = 0; mt < 2; ++mt)
#pragma unroll
        for (int nt = 0; nt < 4; ++nt) {
            int r0 = bm + wm + mt * 16 + g;
            int c0 = bn + wn + nt * 8 + t4 * 2;
            *(float2*)&C[(size_t)r0 * N + c0] =
                make_float2(mst[mt][nt][0], mst[mt][nt][1]);
            *(float2*)&C[(size_t)(r0 + 8) * N + c0] =
                make_float2(mst[mt][nt][2], mst[mt][nt][3]);
        }
}

// ---------------- RoPE + layout transpose (precision-matched) ----------------
__global__ void rope_kernel()
{
    int p = blockIdx.x;
    int hh = blockIdx.y;
    int d = threadIdx.x;

    int i = d & 63;
    float P = (float)pow(10000.0, (double)(2 * i) / 128.0);
    float invf = __fdiv_rn(1.0f, P);
    float ang = __fmul_rn((float)p, invf);
    float c = (float)cos((double)ang);
    float s = (float)sin((double)ang);

    if (hh < NH) {
        const float* base = &g_qlin[(size_t)p * DMODEL + hh * HD];
        float v = base[d];
        float other = (d < 64) ? -base[d + 64] : base[d - 64];
        g_qr[((size_t)hh * QLEN + p) * HD + d] =
            __fadd_rn(__fmul_rn(v, c), __fmul_rn(other, s));
    } else if (hh < NH + NKV) {
        int kvh = hh - NH;
        const float* base = &g_klin[(size_t)p * (NKV * HD) + kvh * HD];
        float v = base[d];
        float other = (d < 64) ? -base[d + 64] : base[d - 64];
        g_kr[((size_t)kvh * QLEN + p) * HD + d] =
            __fadd_rn(__fmul_rn(v, c), __fmul_rn(other, s));
    } else {
        int kvh = hh - NH - NKV;
        g_vr[((size_t)kvh * QLEN + p) * HD + d] =
            g_vlin[(size_t)p * (NKV * HD) + kvh * HD + d];
    }
}

// ---------------- label build: 8 warps per block, one (p,h) per warp ------------
__global__ __launch_bounds__(256) void gqk_kernel(const int* __restrict__ sorted_channel)
{
    int warp = threadIdx.x >> 5;
    int lane = threadIdx.x & 31;
    int p = blockIdx.x;
    int h = blockIdx.y * 8 + warp;

    int j = lane & 15;
    bool isK = lane >= 16;

    int ch = sorted_channel[h * HD + j];
    float t;
    if (!isK) t = g_qr[((size_t)h * QLEN + p) * HD + ch];
    else      t = g_kr[((size_t)(h >> 2) * QLEN + p) * HD + ch];

    float mn = t, mx = t;
#pragma unroll
    for (int off = 1; off < 16; off <<= 1) {
        mn = fminf(mn, __shfl_xor_sync(0xffffffffu, mn, off));
        mx = fmaxf(mx, __shfl_xor_sync(0xffffffffu, mx, off));
    }
    float rng = __fadd_rn(mx, -mn);
    if (rng == 0.0f) rng = 1.0f;
    float scale = __fdiv_rn(15.0f, rng);
    float qv = rintf(__fmul_rn(__fadd_rn(t, -mn), scale));
    qv = fminf(fmaxf(qv, 0.0f), 15.0f);
    float outv = __fadd_rn(__fdiv_rn(qv, scale), mn);

    if (!isK) g_gq[((size_t)h * QLEN + p) * OUTL + j] = outv;
    else      g_gk[((size_t)h * QLEN + p) * OUTL + j] = outv;
}

// ---------------- fused gattn -> stable top-256 -> attn -> softmax -> AV --------
// 512 threads per block: halves trip counts of every serial phase.
#define ATPB 512
#define AWARPS 16

__global__ __launch_bounds__(ATPB) void attn_kernel()
{
    int p = blockIdx.x;
    int h = blockIdx.y;
    int kvh = h >> 2;
    int tid = threadIdx.x;
    int lane = tid & 31;
    int warp = tid >> 5;
    unsigned lmask = (1u << lane) - 1u;

    __shared__ float gq_s[OUTL];
    __shared__ float q_s[HD];
    __shared__ unsigned keys[QLEN];
    __shared__ unsigned hist[256];
    __shared__ unsigned wsum[8];
    __shared__ int kept_idx[KEEP];
    __shared__ float attw[KEEP];
    __shared__ float obuf[3][HD];
    __shared__ unsigned sh_prefix;
    __shared__ int sh_want;
    __shared__ int wcnt[AWARPS];
    __shared__ int wcnt2[AWARPS];
    __shared__ int eqbase_s;
    __shared__ int kbase_s;
    __shared__ float red[AWARPS];
    __shared__ float sh_scalar;

    if (tid < OUTL) gq_s[tid] = g_gq[((size_t)h * QLEN + p) * OUTL + tid];
    if (tid < HD)   q_s[tid] = g_qr[((size_t)h * QLEN + p) * HD + tid];
    if (tid == 0) { eqbase_s = 0; kbase_s = 0; }
    __syncthreads();

    int nvalid = p + 1;

    // 1. gattn keys: strict ascending sequential FMA chain, exact /4.
    for (int j = tid; j < nvalid; j += ATPB) {
        const float* g = &g_gk[((size_t)h * QLEN + j) * OUTL];
        float s = __fmul_rn(g[0], gq_s[0]);
#pragma unroll
        for (int d = 1; d < OUTL; ++d)
            s = __fmaf_rn(g[d], gq_s[d], s);
        s = __fmul_rn(s, 0.25f);
        unsigned u = __float_as_uint(s);
        if ((u << 1) == 0u) u = 0u;
        u ^= (u & 0x80000000u) ? 0xFFFFFFFFu : 0x80000000u;
        keys[j] = u;
    }
    __syncthreads();

    // 2. stable top-KEEP selection (radix threshold + ordered compaction)
    int cnt;
    if (nvalid <= KEEP) {
        for (int j = tid; j < nvalid; j += ATPB) kept_idx[j] = j;
        cnt = nvalid;
        __syncthreads();
    } else {
        unsigned prefix = 0;
        int want = KEEP;
        for (int byte = 3; byte >= 0; --byte) {
            if (tid < 256) hist[tid] = 0;
            __syncthreads();
            int shift = byte * 8;
            unsigned pmask = (byte == 3) ? 0u : (0xFFFFFFFFu << (shift + 8));
            for (int j = tid; j < nvalid; j += ATPB) {
                unsigned u = keys[j];
                if ((u & pmask) == prefix)
                    atomicAdd(&hist[(u >> shift) & 255u], 1u);
            }
            __syncthreads();

            unsigned hv = 0, s = 0;
            if (tid < 256) {
                hv = hist[tid];
                s = hv;
#pragma unroll
                for (int off = 1; off < 32; off <<= 1) {
                    unsigned t2 = __shfl_down_sync(0xffffffffu, s, off);
                    if (lane + off < 32) s += t2;
                }
                if (lane == 0) wsum[warp] = s;
            }
            __syncthreads();
            if (tid < 256) {
                unsigned add = 0;
#pragma unroll
                for (int w = 0; w < 8; ++w)
                    if (w > warp) add += wsum[w];
                unsigned suft = s + add;
                unsigned above = suft - hv;
                if (suft >= (unsigned)want && above < (unsigned)want) {
                    sh_prefix = prefix | ((unsigned)tid << shift);
                    sh_want = want - (int)above;
                }
            }
            __syncthreads();
            prefix = sh_prefix;
            want = sh_want;
            __syncthreads();
        }
        unsigned uT = prefix;
        int r = want;

        // ordered stable compaction: chunks asc, warps asc, lanes asc
#pragma unroll
        for (int chunk = 0; chunk < QLEN / ATPB; ++chunk) {
            int j = chunk * ATPB + tid;
            bool isval = j < nvalid;
            unsigned u = isval ? keys[j] : 0u;
            bool gt = isval && (u > uT);
            bool eq = isval && (u == uT);

            unsigned bal_eq = __ballot_sync(0xffffffffu, eq);
            if (lane == 0) wcnt[warp] = __popc(bal_eq);
            __syncthreads();
            int eqoff = eqbase_s;
            for (int w = 0; w < warp; ++w) eqoff += wcnt[w];
            int eqrank = eqoff + __popc(bal_eq & lmask);
            bool keep = gt || (eq && eqrank < r);

            unsigned bal_k = __ballot_sync(0xffffffffu, keep);
            if (lane == 0) wcnt2[warp] = __popc(bal_k);
            __syncthreads();
            int koff = kbase_s;
            for (int w = 0; w < warp; ++w) koff += wcnt2[w];
            if (keep) kept_idx[koff + __popc(bal_k & lmask)] = j;
            __syncthreads();
            if (tid == 0) {
                int te = 0, tk = 0;
                for (int w = 0; w < AWARPS; ++w) { te += wcnt[w]; tk += wcnt2[w]; }
                eqbase_s += te;
                kbase_s += tk;
            }
            __syncthreads();
        }
        cnt = kbase_s;
    }
    __syncthreads();

    // 3. attn scores on kept columns (warp per column, float4 loads)
    {
        float4 qreg = *(const float4*)&q_s[lane * 4];
        for (int c = warp; c < cnt; c += AWARPS) {
            int j = kept_idx[c];
            float4 kv = *(const float4*)&g_kr[((size_t)kvh * QLEN + j) * HD + lane * 4];
            float s = __fmul_rn(qreg.x, kv.x);
            s = __fmaf_rn(qreg.y, kv.y, s);
            s = __fmaf_rn(qreg.z, kv.z, s);
            s = __fmaf_rn(qreg.w, kv.w, s);
#pragma unroll
            for (int off = 16; off; off >>= 1) s += __shfl_xor_sync(0xffffffffu, s, off);
            if (lane == 0) attw[c] = s / 11.313708498984761f;
        }
    }
    __syncthreads();

    // 4. softmax over kept (exp via double -> correctly rounded fp32)
    float vmax = -FLT_MAX;
    for (int c = tid; c < cnt; c += ATPB) vmax = fmaxf(vmax, attw[c]);
#pragma unroll
    for (int off = 16; off; off >>= 1)
        vmax = fmaxf(vmax, __shfl_xor_sync(0xffffffffu, vmax, off));
    if (lane == 0) red[warp] = vmax;
    __syncthreads();
    if (warp == 0) {
        float m = (lane < AWARPS) ? red[lane] : -FLT_MAX;
#pragma unroll
        for (int off = 8; off; off >>= 1)
            m = fmaxf(m, __shfl_xor_sync(0xffffffffu, m, off));
        if (lane == 0) sh_scalar = m;
    }
    __syncthreads();
    float M = sh_scalar;

    float lsum = 0.f;
    for (int c = tid; c < cnt; c += ATPB) {
        float e = (float)exp((double)__fadd_rn(attw[c], -M));
        attw[c] = e;
        lsum += e;
    }
#pragma unroll
    for (int off = 16; off; off >>= 1)
        lsum += __shfl_xor_sync(0xffffffffu, lsum, off);
    if (lane == 0) red[warp] = lsum;
    __syncthreads();
    if (warp == 0) {
        float s2 = (lane < AWARPS) ? red[lane] : 0.f;
#pragma unroll
        for (int off = 8; off; off >>= 1)
            s2 += __shfl_xor_sync(0xffffffffu, s2, off);
        if (lane == 0) sh_scalar = s2;
    }
    __syncthreads();
    float denom = sh_scalar;

    for (int c = tid; c < cnt; c += ATPB)
        attw[c] = __fdiv_rn(attw[c], denom);
    __syncthreads();

    // 5. AV: 4 column-partitions, reduce via shared
    {
        int d = tid & 127;
        int part = tid >> 7;     // 0..3
        float acc = 0.f;
        const float* vbase = &g_vr[(size_t)kvh * QLEN * HD + d];
        for (int c = part; c < cnt; c += 4)
            acc = __fmaf_rn(attw[c], __ldg(&vbase[(size_t)kept_idx[c] * HD]), acc);
        if (part < 3) obuf[part][d] = acc;
        __syncthreads();
        if (part == 3) {
            float s = __fadd_rn(obuf[0][d], obuf[1][d]);
            s = __fadd_rn(s, obuf[2][d]);
            s = __fadd_rn(s, acc);
            g_o[(size_t)p * (NH * HD) + h * HD + d] = s;
        }
    }
}

// ---------------- launch ----------------
extern "C" void kernel_launch(void* const* d_in, const int* in_sizes, int n_in,
                              void* d_out, int out_size)
{
    const float* hidden = (const float*)d_in[0];
    const float* Wq = (const float*)d_in[3];
    const float* Wk = (const float*)d_in[4];
    const float* Wv = (const float*)d_in[5];
    const float* Wo = (const float*)d_in[6];
    const int* sorted_channel = (const int*)d_in[7];
    float* out = (float*)d_out;

    float *qlin, *klin, *vlin, *o;
    cudaGetSymbolAddress((void**)&qlin, g_qlin);
    cudaGetSymbolAddress((void**)&klin, g_klin);
    cudaGetSymbolAddress((void**)&vlin, g_vlin);
    cudaGetSymbolAddress((void**)&o, g_o);

    dim3 t256(256);
    gemm_tf32<<<dim3(DMODEL / GBN, QLEN / GBM, 1), t256>>>(
        hidden, Wq, qlin, Wq, qlin, DMODEL, DMODEL);
    gemm_tf32<<<dim3((NKV * HD) / GBN, QLEN / GBM, 2), t256>>>(
        hidden, Wk, klin, Wv, vlin, NKV * HD, DMODEL);
    rope_kernel<<<dim3(QLEN, NH + 2 * NKV), 128>>>();
    gqk_kernel<<<dim3(QLEN, NH / 8), t256>>>(sorted_channel);
    attn_kernel<<<dim3(QLEN, NH), ATPB>>>();
    gemm_tf32<<<dim3(DMODEL / GBN, QLEN / GBM, 1), t256>>>(
        o, Wo, out, Wo, out, DMODEL, DMODEL);
}

// round 11
// speedup vs baseline: 1.2773x; 1.1224x over previous
#include <cuda_runtime.h>
#include <math.h>
#include <float.h>

#define QLEN 1024
#define DMODEL 4096
#define NH 32
#define NKV 8
#define HD 128
#define OUTL 16
#define KEEP 256

// ---------------- scratch (static device globals; no allocation) ----------------
__device__ float g_qlin[QLEN * DMODEL];
__device__ float g_klin[QLEN * NKV * HD];
__device__ float g_vlin[QLEN * NKV * HD];
__device__ float g_qr[NH * QLEN * HD];
__device__ float g_kr[NKV * QLEN * HD];
__device__ float g_vr[NKV * QLEN * HD];
__device__ float g_gq[NH * QLEN * OUTL];
__device__ float g_gk[NH * QLEN * OUTL];
__device__ float g_o[QLEN * NH * HD];

// ---------------- 3xTF32 tensor-core GEMM (round-7 form: best measured) ---------
#define GBM 128
#define GBN 64
#define GBK 32
#define SPITCH (GBK + 4)

__device__ __forceinline__ void tf32_split(float x, unsigned& hi, unsigned& lo) {
    unsigned h;
    asm("cvt.rna.tf32.f32 %0, %1;" : "=r"(h) : "f"(x));
    float r = __fadd_rn(x, -__uint_as_float(h));
    unsigned l;
    asm("cvt.rna.tf32.f32 %0, %1;" : "=r"(l) : "f"(r));
    hi = h; lo = l;
}

__device__ __forceinline__ void mma_tf32(float* d, const unsigned* a, const unsigned* b) {
    asm volatile(
        "mma.sync.aligned.m16n8k8.row.col.f32.tf32.tf32.f32 "
        "{%0,%1,%2,%3}, {%4,%5,%6,%7}, {%8,%9}, {%0,%1,%2,%3};"
        : "+f"(d[0]), "+f"(d[1]), "+f"(d[2]), "+f"(d[3])
        : "r"(a[0]), "r"(a[1]), "r"(a[2]), "r"(a[3]), "r"(b[0]), "r"(b[1]));
}

// One launch covers up to 3 independent GEMMs sharing A (selected by blockIdx.z).
// nblk[z] = number of active n-blocks for that gemm; CTAs beyond it exit.
__global__ __launch_bounds__(256) void gemm_tf32(
    const float* __restrict__ A,
    const float* __restrict__ B0, float* __restrict__ C0, int N0,
    const float* __restrict__ B1, float* __restrict__ C1, int N1,
    const float* __restrict__ B2, float* __restrict__ C2, int N2,
    int K)
{
    const float* B;
    float* C;
    int N;
    if (blockIdx.z == 0)      { B = B0; C = C0; N = N0; }
    else if (blockIdx.z == 1) { B = B1; C = C1; N = N1; }
    else                      { B = B2; C = C2; N = N2; }
    if ((int)blockIdx.x * GBN >= N) return;     // uniform over CTA, safe

    __shared__ float As[GBM][SPITCH];
    __shared__ float Bs[GBN][SPITCH];

    int tid = threadIdx.x;
    int lane = tid & 31;
    int wid = tid >> 5;
    int wm = (wid >> 1) * 32;
    int wn = (wid & 1) * 32;
    int g = lane >> 2;
    int t4 = lane & 3;

    int bm = blockIdx.y * GBM;
    int bn = blockIdx.x * GBN;

    float acc[2][4][4];
    float mst[2][4][4];
#pragma unroll
    for (int mt = 0; mt < 2; ++mt)
#pragma unroll
        for (int nt = 0; nt < 4; ++nt)
#pragma unroll
            for (int r = 0; r < 4; ++r) { acc[mt][nt][r] = 0.f; mst[mt][nt][r] = 0.f; }

    int ntiles = K / GBK;
    for (int t = 0; t < ntiles; ++t) {
        int k0 = t * GBK;
#pragma unroll
        for (int i = 0; i < 4; ++i) {
            int idx = tid + i * 256;
            int r = idx >> 3;
            int c = (idx & 7) << 2;
            float4 v = *(const float4*)&A[(size_t)(bm + r) * K + k0 + c];
            *(float4*)&As[r][c] = v;
        }
#pragma unroll
        for (int i = 0; i < 2; ++i) {
            int idx = tid + i * 256;
            int k = idx >> 4;
            int n4 = (idx & 15) << 2;
            float4 v = *(const float4*)&B[(size_t)(k0 + k) * N + bn + n4];
            Bs[n4 + 0][k] = v.x;
            Bs[n4 + 1][k] = v.y;
            Bs[n4 + 2][k] = v.z;
            Bs[n4 + 3][k] = v.w;
        }
        __syncthreads();

#pragma unroll
        for (int ks = 0; ks < GBK / 8; ++ks) {
            int kb = ks * 8;
            unsigned ah[2][4], al[2][4];
#pragma unroll
            for (int mt = 0; mt < 2; ++mt) {
                int r0 = wm + mt * 16;
                tf32_split(As[r0 + g][kb + t4],          ah[mt][0], al[mt][0]);
                tf32_split(As[r0 + g + 8][kb + t4],      ah[mt][1], al[mt][1]);
                tf32_split(As[r0 + g][kb + t4 + 4],      ah[mt][2], al[mt][2]);
                tf32_split(As[r0 + g + 8][kb + t4 + 4],  ah[mt][3], al[mt][3]);
            }
            unsigned bh[4][2], bl[4][2];
#pragma unroll
            for (int nt = 0; nt < 4; ++nt) {
                int col = wn + nt * 8 + g;
                tf32_split(Bs[col][kb + t4],     bh[nt][0], bl[nt][0]);
                tf32_split(Bs[col][kb + t4 + 4], bh[nt][1], bl[nt][1]);
            }
#pragma unroll
            for (int mt = 0; mt < 2; ++mt)
#pragma unroll
                for (int nt = 0; nt < 4; ++nt) {
                    mma_tf32(acc[mt][nt], ah[mt], bh[nt]);
                    mma_tf32(acc[mt][nt], al[mt], bh[nt]);
                    mma_tf32(acc[mt][nt], ah[mt], bl[nt]);
                }
        }
        __syncthreads();

        if ((t & 3) == 3) {
#pragma unroll
            for (int mt = 0; mt < 2; ++mt)
#pragma unroll
                for (int nt = 0; nt < 4; ++nt)
#pragma unroll
                    for (int r = 0; r < 4; ++r) {
                        mst[mt][nt][r] = __fadd_rn(mst[mt][nt][r], acc[mt][nt][r]);
                        acc[mt][nt][r] = 0.f;
                    }
        }
    }

#pragma unroll
    for (int mt = 0; mt < 2; ++mt)
#pragma unroll
        for (int nt = 0; nt < 4; ++nt) {
            int r0 = bm + wm + mt * 16 + g;
            int c0 = bn + wn + nt * 8 + t4 * 2;
            *(float2*)&C[(size_t)r0 * N + c0] =
                make_float2(mst[mt][nt][0], mst[mt][nt][1]);
            *(float2*)&C[(size_t)(r0 + 8) * N + c0] =
                make_float2(mst[mt][nt][2], mst[mt][nt][3]);
        }
}

// ---------------- RoPE + layout transpose (precision-matched) ----------------
__global__ void rope_kernel()
{
    int p = blockIdx.x;
    int hh = blockIdx.y;
    int d = threadIdx.x;

    int i = d & 63;
    float P = (float)pow(10000.0, (double)(2 * i) / 128.0);
    float invf = __fdiv_rn(1.0f, P);
    float ang = __fmul_rn((float)p, invf);
    float c = (float)cos((double)ang);
    float s = (float)sin((double)ang);

    if (hh < NH) {
        const float* base = &g_qlin[(size_t)p * DMODEL + hh * HD];
        float v = base[d];
        float other = (d < 64) ? -base[d + 64] : base[d - 64];
        g_qr[((size_t)hh * QLEN + p) * HD + d] =
            __fadd_rn(__fmul_rn(v, c), __fmul_rn(other, s));
    } else if (hh < NH + NKV) {
        int kvh = hh - NH;
        const float* base = &g_klin[(size_t)p * (NKV * HD) + kvh * HD];
        float v = base[d];
        float other = (d < 64) ? -base[d + 64] : base[d - 64];
        g_kr[((size_t)kvh * QLEN + p) * HD + d] =
            __fadd_rn(__fmul_rn(v, c), __fmul_rn(other, s));
    } else {
        int kvh = hh - NH - NKV;
        g_vr[((size_t)kvh * QLEN + p) * HD + d] =
            g_vlin[(size_t)p * (NKV * HD) + kvh * HD + d];
    }
}

// ---------------- label build: 8 warps per block, one (p,h) per warp ------------
__global__ __launch_bounds__(256) void gqk_kernel(const int* __restrict__ sorted_channel)
{
    int warp = threadIdx.x >> 5;
    int lane = threadIdx.x & 31;
    int p = blockIdx.x;
    int h = blockIdx.y * 8 + warp;

    int j = lane & 15;
    bool isK = lane >= 16;

    int ch = sorted_channel[h * HD + j];
    float t;
    if (!isK) t = g_qr[((size_t)h * QLEN + p) * HD + ch];
    else      t = g_kr[((size_t)(h >> 2) * QLEN + p) * HD + ch];

    float mn = t, mx = t;
#pragma unroll
    for (int off = 1; off < 16; off <<= 1) {
        mn = fminf(mn, __shfl_xor_sync(0xffffffffu, mn, off));
        mx = fmaxf(mx, __shfl_xor_sync(0xffffffffu, mx, off));
    }
    float rng = __fadd_rn(mx, -mn);
    if (rng == 0.0f) rng = 1.0f;
    float scale = __fdiv_rn(15.0f, rng);
    float qv = rintf(__fmul_rn(__fadd_rn(t, -mn), scale));
    qv = fminf(fmaxf(qv, 0.0f), 15.0f);
    float outv = __fadd_rn(__fdiv_rn(qv, scale), mn);

    if (!isK) g_gq[((size_t)h * QLEN + p) * OUTL + j] = outv;
    else      g_gk[((size_t)h * QLEN + p) * OUTL + j] = outv;
}

// ---------------- fused gattn -> stable top-256 -> attn -> softmax -> AV ----
__global__ __launch_bounds__(256) void attn_kernel()
{
    int p = blockIdx.x;
    int h = blockIdx.y;
    int kvh = h >> 2;
    int tid = threadIdx.x;
    int lane = tid & 31;
    int warp = tid >> 5;
    unsigned lmask = (1u << lane) - 1u;

    __shared__ float gq_s[OUTL];
    __shared__ float q_s[HD];
    __shared__ unsigned keys[QLEN];
    __shared__ unsigned hist[256];
    __shared__ unsigned wsum[8];
    __shared__ int kept_idx[KEEP];
    __shared__ float attw[KEEP];
    __shared__ float obuf[HD];
    __shared__ unsigned sh_prefix;
    __shared__ int sh_want;
    __shared__ int wcnt[8];
    __shared__ int wcnt2[8];
    __shared__ int eqbase_s;
    __shared__ int kbase_s;
    __shared__ float red[8];
    __shared__ float sh_scalar;

    if (tid < OUTL) gq_s[tid] = g_gq[((size_t)h * QLEN + p) * OUTL + tid];
    if (tid < HD)   q_s[tid] = g_qr[((size_t)h * QLEN + p) * HD + tid];
    if (tid == 0) { eqbase_s = 0; kbase_s = 0; }
    __syncthreads();

    int nvalid = p + 1;

    // 1. gattn keys: strict ascending sequential FMA chain, exact /4.
    for (int j = tid; j < nvalid; j += 256) {
        const float* g = &g_gk[((size_t)h * QLEN + j) * OUTL];
        float s = __fmul_rn(g[0], gq_s[0]);
#pragma unroll
        for (int d = 1; d < OUTL; ++d)
            s = __fmaf_rn(g[d], gq_s[d], s);
        s = __fmul_rn(s, 0.25f);
        unsigned u = __float_as_uint(s);
        if ((u << 1) == 0u) u = 0u;
        u ^= (u & 0x80000000u) ? 0xFFFFFFFFu : 0x80000000u;
        keys[j] = u;
    }
    __syncthreads();

    // 2. stable top-KEEP selection (radix threshold + ordered compaction)
    int cnt;
    if (nvalid <= KEEP) {
        for (int j = tid; j < nvalid; j += 256) kept_idx[j] = j;
        cnt = nvalid;
        __syncthreads();
    } else {
        unsigned prefix = 0;
        int want = KEEP;
        for (int byte = 3; byte >= 0; --byte) {
            hist[tid] = 0;
            __syncthreads();
            int shift = byte * 8;
            unsigned pmask = (byte == 3) ? 0u : (0xFFFFFFFFu << (shift + 8));
            for (int j = tid; j < nvalid; j += 256) {
                unsigned u = keys[j];
                if ((u & pmask) == prefix)
                    atomicAdd(&hist[(u >> shift) & 255u], 1u);
            }
            __syncthreads();

            unsigned hv = hist[tid];
            unsigned s = hv;
#pragma unroll
            for (int off = 1; off < 32; off <<= 1) {
                unsigned t2 = __shfl_down_sync(0xffffffffu, s, off);
                if (lane + off < 32) s += t2;
            }
            if (lane == 0) wsum[warp] = s;
            __syncthreads();
            unsigned add = 0;
#pragma unroll
            for (int w = 0; w < 8; ++w)
                if (w > warp) add += wsum[w];
            unsigned suft = s + add;
            unsigned above = suft - hv;
            if (suft >= (unsigned)want && above < (unsigned)want) {
                sh_prefix = prefix | ((unsigned)tid << shift);
                sh_want = want - (int)above;
            }
            __syncthreads();
            prefix = sh_prefix;
            want = sh_want;
            __syncthreads();
        }
        unsigned uT = prefix;
        int r = want;

        // ordered stable compaction: chunks asc, warps asc, lanes asc
#pragma unroll
        for (int chunk = 0; chunk < QLEN / 256; ++chunk) {
            int j = chunk * 256 + tid;
            bool isval = j < nvalid;
            unsigned u = isval ? keys[j] : 0u;
            bool gt = isval && (u > uT);
            bool eq = isval && (u == uT);

            unsigned bal_eq = __ballot_sync(0xffffffffu, eq);
            if (lane == 0) wcnt[warp] = __popc(bal_eq);
            __syncthreads();
            int eqoff = eqbase_s;
            for (int w = 0; w < warp; ++w) eqoff += wcnt[w];
            int eqrank = eqoff + __popc(bal_eq & lmask);
            bool keep = gt || (eq && eqrank < r);

            unsigned bal_k = __ballot_sync(0xffffffffu, keep);
            if (lane == 0) wcnt2[warp] = __popc(bal_k);
            __syncthreads();
            int koff = kbase_s;
            for (int w = 0; w < warp; ++w) koff += wcnt2[w];
            if (keep) kept_idx[koff + __popc(bal_k & lmask)] = j;
            __syncthreads();
            if (tid == 0) {
                int te = 0, tk = 0;
                for (int w = 0; w < 8; ++w) { te += wcnt[w]; tk += wcnt2[w]; }
                eqbase_s += te;
                kbase_s += tk;
            }
            __syncthreads();
        }
        cnt = kbase_s;
    }
    __syncthreads();

    // 3. attn scores on kept columns (warp per column, float4 loads)
    {
        float4 qreg = *(const float4*)&q_s[lane * 4];
        for (int c = warp; c < cnt; c += 8) {
            int j = kept_idx[c];
            float4 kv = *(const float4*)&g_kr[((size_t)kvh * QLEN + j) * HD + lane * 4];
            float s = __fmul_rn(qreg.x, kv.x);
            s = __fmaf_rn(qreg.y, kv.y, s);
            s = __fmaf_rn(qreg.z, kv.z, s);
            s = __fmaf_rn(qreg.w, kv.w, s);
#pragma unroll
            for (int off = 16; off; off >>= 1) s += __shfl_xor_sync(0xffffffffu, s, off);
            if (lane == 0) attw[c] = s / 11.313708498984761f;
        }
    }
    __syncthreads();

    // 4. softmax over kept (expf: post-selection, ulp noise only)
    float vmax = -FLT_MAX;
    for (int c = tid; c < cnt; c += 256) vmax = fmaxf(vmax, attw[c]);
#pragma unroll
    for (int off = 16; off; off >>= 1)
        vmax = fmaxf(vmax, __shfl_xor_sync(0xffffffffu, vmax, off));
    if (lane == 0) red[warp] = vmax;
    __syncthreads();
    if (warp == 0) {
        float m = (lane < 8) ? red[lane] : -FLT_MAX;
#pragma unroll
        for (int off = 4; off; off >>= 1)
            m = fmaxf(m, __shfl_xor_sync(0xffffffffu, m, off));
        if (lane == 0) sh_scalar = m;
    }
    __syncthreads();
    float M = sh_scalar;

    float lsum = 0.f;
    for (int c = tid; c < cnt; c += 256) {
        float e = expf(__fadd_rn(attw[c], -M));
        attw[c] = e;
        lsum += e;
    }
#pragma unroll
    for (int off = 16; off; off >>= 1)
        lsum += __shfl_xor_sync(0xffffffffu, lsum, off);
    if (lane == 0) red[warp] = lsum;
    __syncthreads();
    if (warp == 0) {
        float s2 = (lane < 8) ? red[lane] : 0.f;
#pragma unroll
        for (int off = 4; off; off >>= 1)
            s2 += __shfl_xor_sync(0xffffffffu, s2, off);
        if (lane == 0) sh_scalar = s2;
    }
    __syncthreads();
    float denom = sh_scalar;

    for (int c = tid; c < cnt; c += 256)
        attw[c] = __fdiv_rn(attw[c], denom);
    __syncthreads();

    // 5. AV: two halves of the block split the kept columns
    {
        int d = tid & 127;
        int half = tid >> 7;
        float acc = 0.f;
        const float* vbase = &g_vr[(size_t)kvh * QLEN * HD + d];
        for (int c = half; c < cnt; c += 2)
            acc = __fmaf_rn(attw[c], __ldg(&vbase[(size_t)kept_idx[c] * HD]), acc);
        if (half == 0) obuf[d] = acc;
        __syncthreads();
        if (half == 1)
            g_o[(size_t)p * (NH * HD) + h * HD + d] = __fadd_rn(obuf[d], acc);
    }
}

// ---------------- launch ----------------
extern "C" void kernel_launch(void* const* d_in, const int* in_sizes, int n_in,
                              void* d_out, int out_size)
{
    const float* hidden = (const float*)d_in[0];
    const float* Wq = (const float*)d_in[3];
    const float* Wk = (const float*)d_in[4];
    const float* Wv = (const float*)d_in[5];
    const float* Wo = (const float*)d_in[6];
    const int* sorted_channel = (const int*)d_in[7];
    float* out = (float*)d_out;

    float *qlin, *klin, *vlin, *o;
    cudaGetSymbolAddress((void**)&qlin, g_qlin);
    cudaGetSymbolAddress((void**)&klin, g_klin);
    cudaGetSymbolAddress((void**)&vlin, g_vlin);
    cudaGetSymbolAddress((void**)&o, g_o);

    dim3 t256(256);
    // Q, K, V projections fused into one launch (z = 0,1,2; unused CTAs exit)
    gemm_tf32<<<dim3(DMODEL / GBN, QLEN / GBM, 3), t256>>>(
        hidden,
        Wq, qlin, DMODEL,
        Wk, klin, NKV * HD,
        Wv, vlin, NKV * HD,
        DMODEL);
    rope_kernel<<<dim3(QLEN, NH + 2 * NKV), 128>>>();
    gqk_kernel<<<dim3(QLEN, NH / 8), t256>>>(sorted_channel);
    attn_kernel<<<dim3(QLEN, NH), t256>>>();
    // output projection
    gemm_tf32<<<dim3(DMODEL / GBN, QLEN / GBM, 1), t256>>>(
        o,
        Wo, out, DMODEL,
        Wo, out, DMODEL,
        Wo, out, DMODEL,
        DMODEL);
}

// round 12
// speedup vs baseline: 1.3178x; 1.0317x over previous
#include <cuda_runtime.h>
#include <math.h>
#include <float.h>

#define QLEN 1024
#define DMODEL 4096
#define NH 32
#define NKV 8
#define HD 128
#define OUTL 16
#define KEEP 256

// ---------------- scratch (static device globals; no allocation) ----------------
__device__ float g_qlin[QLEN * DMODEL];
__device__ float g_klin[QLEN * NKV * HD];
__device__ float g_vlin[QLEN * NKV * HD];
__device__ float g_qr[NH * QLEN * HD];
__device__ float g_kr[NKV * QLEN * HD];
__device__ float g_vr[NKV * QLEN * HD];
__device__ float g_gq[NH * QLEN * OUTL];
__device__ float g_gk[NH * QLEN * OUTL];
__device__ float g_o[QLEN * NH * HD];

// ---------------- 3xTF32 tensor-core GEMM, double-buffered smem -----------------
// Compute path (splits, MMA order, folds) byte-identical to the round-7 form.
#define GBM 128
#define GBN 64
#define GBK 32
#define SPITCH (GBK + 4)
#define SMEM_A_FLOATS (2 * GBM * SPITCH)
#define SMEM_B_FLOATS (2 * GBN * SPITCH)
#define SMEM_BYTES ((SMEM_A_FLOATS + SMEM_B_FLOATS) * 4)

__device__ __forceinline__ void tf32_split(float x, unsigned& hi, unsigned& lo) {
    unsigned h;
    asm("cvt.rna.tf32.f32 %0, %1;" : "=r"(h) : "f"(x));
    float r = __fadd_rn(x, -__uint_as_float(h));
    unsigned l;
    asm("cvt.rna.tf32.f32 %0, %1;" : "=r"(l) : "f"(r));
    hi = h; lo = l;
}

__device__ __forceinline__ void mma_tf32(float* d, const unsigned* a, const unsigned* b) {
    asm volatile(
        "mma.sync.aligned.m16n8k8.row.col.f32.tf32.tf32.f32 "
        "{%0,%1,%2,%3}, {%4,%5,%6,%7}, {%8,%9}, {%0,%1,%2,%3};"
        : "+f"(d[0]), "+f"(d[1]), "+f"(d[2]), "+f"(d[3])
        : "r"(a[0]), "r"(a[1]), "r"(a[2]), "r"(a[3]), "r"(b[0]), "r"(b[1]));
}

__global__ __launch_bounds__(256, 2) void gemm_tf32(
    const float* __restrict__ A,
    const float* __restrict__ B0, float* __restrict__ C0, int N0,
    const float* __restrict__ B1, float* __restrict__ C1, int N1,
    const float* __restrict__ B2, float* __restrict__ C2, int N2,
    int K)
{
    const float* B;
    float* C;
    int N;
    if (blockIdx.z == 0)      { B = B0; C = C0; N = N0; }
    else if (blockIdx.z == 1) { B = B1; C = C1; N = N1; }
    else                      { B = B2; C = C2; N = N2; }
    if ((int)blockIdx.x * GBN >= N) return;

    extern __shared__ float smem_dyn[];
    float (*As)[GBM][SPITCH] = (float(*)[GBM][SPITCH])smem_dyn;
    float (*Bs)[GBN][SPITCH] = (float(*)[GBN][SPITCH])(smem_dyn + SMEM_A_FLOATS);

    int tid = threadIdx.x;
    int lane = tid & 31;
    int wid = tid >> 5;
    int wm = (wid >> 1) * 32;
    int wn = (wid & 1) * 32;
    int g = lane >> 2;
    int t4 = lane & 3;

    int bm = blockIdx.y * GBM;
    int bn = blockIdx.x * GBN;

    // per-thread load coords
    int arow[4], acol[4];
#pragma unroll
    for (int i = 0; i < 4; ++i) {
        int idx = tid + i * 256;
        arow[i] = idx >> 3;
        acol[i] = (idx & 7) << 2;
    }
    int bkrow[2], bncol[2];
#pragma unroll
    for (int i = 0; i < 2; ++i) {
        int idx = tid + i * 256;
        bkrow[i] = idx >> 4;
        bncol[i] = (idx & 15) << 2;
    }

    float acc[2][4][4], mst[2][4][4];
#pragma unroll
    for (int mt = 0; mt < 2; ++mt)
#pragma unroll
        for (int nt = 0; nt < 4; ++nt)
#pragma unroll
            for (int r = 0; r < 4; ++r) { acc[mt][nt][r] = 0.f; mst[mt][nt][r] = 0.f; }

    float4 ra[4], rb[2];
    // tile 0 -> regs -> buf 0
#pragma unroll
    for (int i = 0; i < 4; ++i)
        ra[i] = *(const float4*)&A[(size_t)(bm + arow[i]) * K + acol[i]];
#pragma unroll
    for (int i = 0; i < 2; ++i)
        rb[i] = *(const float4*)&B[(size_t)bkrow[i] * N + bn + bncol[i]];
#pragma unroll
    for (int i = 0; i < 4; ++i)
        *(float4*)&As[0][arow[i]][acol[i]] = ra[i];
#pragma unroll
    for (int i = 0; i < 2; ++i) {
        Bs[0][bncol[i] + 0][bkrow[i]] = rb[i].x;
        Bs[0][bncol[i] + 1][bkrow[i]] = rb[i].y;
        Bs[0][bncol[i] + 2][bkrow[i]] = rb[i].z;
        Bs[0][bncol[i] + 3][bkrow[i]] = rb[i].w;
    }
    __syncthreads();

    int ntiles = K / GBK;
    for (int t = 0; t < ntiles; ++t) {
        int cur = t & 1;
        int nxt = cur ^ 1;

        // issue next tile's global loads before the MMA burst
        if (t + 1 < ntiles) {
            int k0 = (t + 1) * GBK;
#pragma unroll
            for (int i = 0; i < 4; ++i)
                ra[i] = *(const float4*)&A[(size_t)(bm + arow[i]) * K + k0 + acol[i]];
#pragma unroll
            for (int i = 0; i < 2; ++i)
                rb[i] = *(const float4*)&B[(size_t)(k0 + bkrow[i]) * N + bn + bncol[i]];
        }

        // compute on buf[cur]
#pragma unroll
        for (int ks = 0; ks < GBK / 8; ++ks) {
            int kb = ks * 8;
            unsigned ah[2][4], al[2][4];
#pragma unroll
            for (int mt = 0; mt < 2; ++mt) {
                int r0 = wm + mt * 16;
                tf32_split(As[cur][r0 + g][kb + t4],          ah[mt][0], al[mt][0]);
                tf32_split(As[cur][r0 + g + 8][kb + t4],      ah[mt][1], al[mt][1]);
                tf32_split(As[cur][r0 + g][kb + t4 + 4],      ah[mt][2], al[mt][2]);
                tf32_split(As[cur][r0 + g + 8][kb + t4 + 4],  ah[mt][3], al[mt][3]);
            }
            unsigned bh[4][2], bl[4][2];
#pragma unroll
            for (int nt = 0; nt < 4; ++nt) {
                int col = wn + nt * 8 + g;
                tf32_split(Bs[cur][col][kb + t4],     bh[nt][0], bl[nt][0]);
                tf32_split(Bs[cur][col][kb + t4 + 4], bh[nt][1], bl[nt][1]);
            }
#pragma unroll
            for (int mt = 0; mt < 2; ++mt)
#pragma unroll
                for (int nt = 0; nt < 4; ++nt) {
                    mma_tf32(acc[mt][nt], ah[mt], bh[nt]);
                    mma_tf32(acc[mt][nt], al[mt], bh[nt]);
                    mma_tf32(acc[mt][nt], ah[mt], bl[nt]);
                }
        }

        // stage next tile into the idle buffer (no sync needed before)
        if (t + 1 < ntiles) {
#pragma unroll
            for (int i = 0; i < 4; ++i)
                *(float4*)&As[nxt][arow[i]][acol[i]] = ra[i];
#pragma unroll
            for (int i = 0; i < 2; ++i) {
                Bs[nxt][bncol[i] + 0][bkrow[i]] = rb[i].x;
                Bs[nxt][bncol[i] + 1][bkrow[i]] = rb[i].y;
                Bs[nxt][bncol[i] + 2][bkrow[i]] = rb[i].z;
                Bs[nxt][bncol[i] + 3][bkrow[i]] = rb[i].w;
            }
        }
        __syncthreads();

        if ((t & 3) == 3) {
#pragma unroll
            for (int mt = 0; mt < 2; ++mt)
#pragma unroll
                for (int nt = 0; nt < 4; ++nt)
#pragma unroll
                    for (int r = 0; r < 4; ++r) {
                        mst[mt][nt][r] = __fadd_rn(mst[mt][nt][r], acc[mt][nt][r]);
                        acc[mt][nt][r] = 0.f;
                    }
        }
    }

#pragma unroll
    for (int mt = 0; mt < 2; ++mt)
#pragma unroll
        for (int nt = 0; nt < 4; ++nt) {
            int r0 = bm + wm + mt * 16 + g;
            int c0 = bn + wn + nt * 8 + t4 * 2;
            *(float2*)&C[(size_t)r0 * N + c0] =
                make_float2(mst[mt][nt][0], mst[mt][nt][1]);
            *(float2*)&C[(size_t)(r0 + 8) * N + c0] =
                make_float2(mst[mt][nt][2], mst[mt][nt][3]);
        }
}

// ---------------- RoPE + layout transpose (precision-matched) ----------------
__global__ void rope_kernel()
{
    int p = blockIdx.x;
    int hh = blockIdx.y;
    int d = threadIdx.x;

    int i = d & 63;
    float P = (float)pow(10000.0, (double)(2 * i) / 128.0);
    float invf = __fdiv_rn(1.0f, P);
    float ang = __fmul_rn((float)p, invf);
    float c = (float)cos((double)ang);
    float s = (float)sin((double)ang);

    if (hh < NH) {
        const float* base = &g_qlin[(size_t)p * DMODEL + hh * HD];
        float v = base[d];
        float other = (d < 64) ? -base[d + 64] : base[d - 64];
        g_qr[((size_t)hh * QLEN + p) * HD + d] =
            __fadd_rn(__fmul_rn(v, c), __fmul_rn(other, s));
    } else if (hh < NH + NKV) {
        int kvh = hh - NH;
        const float* base = &g_klin[(size_t)p * (NKV * HD) + kvh * HD];
        float v = base[d];
        float other = (d < 64) ? -base[d + 64] : base[d - 64];
        g_kr[((size_t)kvh * QLEN + p) * HD + d] =
            __fadd_rn(__fmul_rn(v, c), __fmul_rn(other, s));
    } else {
        int kvh = hh - NH - NKV;
        g_vr[((size_t)kvh * QLEN + p) * HD + d] =
            g_vlin[(size_t)p * (NKV * HD) + kvh * HD + d];
    }
}

// ---------------- label build: 8 warps per block, one (p,h) per warp ------------
__global__ __launch_bounds__(256) void gqk_kernel(const int* __restrict__ sorted_channel)
{
    int warp = threadIdx.x >> 5;
    int lane = threadIdx.x & 31;
    int p = blockIdx.x;
    int h = blockIdx.y * 8 + warp;

    int j = lane & 15;
    bool isK = lane >= 16;

    int ch = sorted_channel[h * HD + j];
    float t;
    if (!isK) t = g_qr[((size_t)h * QLEN + p) * HD + ch];
    else      t = g_kr[((size_t)(h >> 2) * QLEN + p) * HD + ch];

    float mn = t, mx = t;
#pragma unroll
    for (int off = 1; off < 16; off <<= 1) {
        mn = fminf(mn, __shfl_xor_sync(0xffffffffu, mn, off));
        mx = fmaxf(mx, __shfl_xor_sync(0xffffffffu, mx, off));
    }
    float rng = __fadd_rn(mx, -mn);
    if (rng == 0.0f) rng = 1.0f;
    float scale = __fdiv_rn(15.0f, rng);
    float qv = rintf(__fmul_rn(__fadd_rn(t, -mn), scale));
    qv = fminf(fmaxf(qv, 0.0f), 15.0f);
    float outv = __fadd_rn(__fdiv_rn(qv, scale), mn);

    if (!isK) g_gq[((size_t)h * QLEN + p) * OUTL + j] = outv;
    else      g_gk[((size_t)h * QLEN + p) * OUTL + j] = outv;
}

// ---------------- fused gattn -> stable top-256 -> attn -> softmax -> AV ----
__global__ __launch_bounds__(256) void attn_kernel()
{
    int p = blockIdx.x;
    int h = blockIdx.y;
    int kvh = h >> 2;
    int tid = threadIdx.x;
    int lane = tid & 31;
    int warp = tid >> 5;
    unsigned lmask = (1u << lane) - 1u;

    __shared__ float gq_s[OUTL];
    __shared__ float q_s[HD];
    __shared__ unsigned keys[QLEN];
    __shared__ unsigned hist[256];
    __shared__ unsigned wsum[8];
    __shared__ int kept_idx[KEEP];
    __shared__ float attw[KEEP];
    __shared__ float obuf[HD];
    __shared__ unsigned sh_prefix;
    __shared__ int sh_want;
    __shared__ int wcnt[8];
    __shared__ int wcnt2[8];
    __shared__ int eqbase_s;
    __shared__ int kbase_s;
    __shared__ float red[8];
    __shared__ float sh_scalar;

    if (tid < OUTL) gq_s[tid] = g_gq[((size_t)h * QLEN + p) * OUTL + tid];
    if (tid < HD)   q_s[tid] = g_qr[((size_t)h * QLEN + p) * HD + tid];
    if (tid == 0) { eqbase_s = 0; kbase_s = 0; }
    __syncthreads();

    int nvalid = p + 1;

    // 1. gattn keys: strict ascending sequential FMA chain, exact /4.
    for (int j = tid; j < nvalid; j += 256) {
        const float* g = &g_gk[((size_t)h * QLEN + j) * OUTL];
        float s = __fmul_rn(g[0], gq_s[0]);
#pragma unroll
        for (int d = 1; d < OUTL; ++d)
            s = __fmaf_rn(g[d], gq_s[d], s);
        s = __fmul_rn(s, 0.25f);
        unsigned u = __float_as_uint(s);
        if ((u << 1) == 0u) u = 0u;
        u ^= (u & 0x80000000u) ? 0xFFFFFFFFu : 0x80000000u;
        keys[j] = u;
    }
    __syncthreads();

    // 2. stable top-KEEP selection (radix threshold + ordered compaction)
    int cnt;
    if (nvalid <= KEEP) {
        for (int j = tid; j < nvalid; j += 256) kept_idx[j] = j;
        cnt = nvalid;
        __syncthreads();
    } else {
        unsigned prefix = 0;
        int want = KEEP;
        for (int byte = 3; byte >= 0; --byte) {
            hist[tid] = 0;
            __syncthreads();
            int shift = byte * 8;
            unsigned pmask = (byte == 3) ? 0u : (0xFFFFFFFFu << (shift + 8));
            for (int j = tid; j < nvalid; j += 256) {
                unsigned u = keys[j];
                if ((u & pmask) == prefix)
                    atomicAdd(&hist[(u >> shift) & 255u], 1u);
            }
            __syncthreads();

            unsigned hv = hist[tid];
            unsigned s = hv;
#pragma unroll
            for (int off = 1; off < 32; off <<= 1) {
                unsigned t2 = __shfl_down_sync(0xffffffffu, s, off);
                if (lane + off < 32) s += t2;
            }
            if (lane == 0) wsum[warp] = s;
            __syncthreads();
            unsigned add = 0;
#pragma unroll
            for (int w = 0; w < 8; ++w)
                if (w > warp) add += wsum[w];
            unsigned suft = s + add;
            unsigned above = suft - hv;
            if (suft >= (unsigned)want && above < (unsigned)want) {
                sh_prefix = prefix | ((unsigned)tid << shift);
                sh_want = want - (int)above;
            }
            __syncthreads();
            prefix = sh_prefix;
            want = sh_want;
            __syncthreads();
        }
        unsigned uT = prefix;
        int r = want;

        // ordered stable compaction: chunks asc, warps asc, lanes asc
#pragma unroll
        for (int chunk = 0; chunk < QLEN / 256; ++chunk) {
            int j = chunk * 256 + tid;
            bool isval = j < nvalid;
            unsigned u = isval ? keys[j] : 0u;
            bool gt = isval && (u > uT);
            bool eq = isval && (u == uT);

            unsigned bal_eq = __ballot_sync(0xffffffffu, eq);
            if (lane == 0) wcnt[warp] = __popc(bal_eq);
            __syncthreads();
            int eqoff = eqbase_s;
            for (int w = 0; w < warp; ++w) eqoff += wcnt[w];
            int eqrank = eqoff + __popc(bal_eq & lmask);
            bool keep = gt || (eq && eqrank < r);

            unsigned bal_k = __ballot_sync(0xffffffffu, keep);
            if (lane == 0) wcnt2[warp] = __popc(bal_k);
            __syncthreads();
            int koff = kbase_s;
            for (int w = 0; w < warp; ++w) koff += wcnt2[w];
            if (keep) kept_idx[koff + __popc(bal_k & lmask)] = j;
            __syncthreads();
            if (tid == 0) {
                int te = 0, tk = 0;
                for (int w = 0; w < 8; ++w) { te += wcnt[w]; tk += wcnt2[w]; }
                eqbase_s += te;
                kbase_s += tk;
            }
            __syncthreads();
        }
        cnt = kbase_s;
    }
    __syncthreads();

    // 3. attn scores on kept columns (warp per column, float4 loads)
    {
        float4 qreg = *(const float4*)&q_s[lane * 4];
        for (int c = warp; c < cnt; c += 8) {
            int j = kept_idx[c];
            float4 kv = *(const float4*)&g_kr[((size_t)kvh * QLEN + j) * HD + lane * 4];
            float s = __fmul_rn(qreg.x, kv.x);
            s = __fmaf_rn(qreg.y, kv.y, s);
            s = __fmaf_rn(qreg.z, kv.z, s);
            s = __fmaf_rn(qreg.w, kv.w, s);
#pragma unroll
            for (int off = 16; off; off >>= 1) s += __shfl_xor_sync(0xffffffffu, s, off);
            if (lane == 0) attw[c] = s / 11.313708498984761f;
        }
    }
    __syncthreads();

    // 4. softmax over kept (expf: post-selection, ulp noise only)
    float vmax = -FLT_MAX;
    for (int c = tid; c < cnt; c += 256) vmax = fmaxf(vmax, attw[c]);
#pragma unroll
    for (int off = 16; off; off >>= 1)
        vmax = fmaxf(vmax, __shfl_xor_sync(0xffffffffu, vmax, off));
    if (lane == 0) red[warp] = vmax;
    __syncthreads();
    if (warp == 0) {
        float m = (lane < 8) ? red[lane] : -FLT_MAX;
#pragma unroll
        for (int off = 4; off; off >>= 1)
            m = fmaxf(m, __shfl_xor_sync(0xffffffffu, m, off));
        if (lane == 0) sh_scalar = m;
    }
    __syncthreads();
    float M = sh_scalar;

    float lsum = 0.f;
    for (int c = tid; c < cnt; c += 256) {
        float e = expf(__fadd_rn(attw[c], -M));
        attw[c] = e;
        lsum += e;
    }
#pragma unroll
    for (int off = 16; off; off >>= 1)
        lsum += __shfl_xor_sync(0xffffffffu, lsum, off);
    if (lane == 0) red[warp] = lsum;
    __syncthreads();
    if (warp == 0) {
        float s2 = (lane < 8) ? red[lane] : 0.f;
#pragma unroll
        for (int off = 4; off; off >>= 1)
            s2 += __shfl_xor_sync(0xffffffffu, s2, off);
        if (lane == 0) sh_scalar = s2;
    }
    __syncthreads();
    float denom = sh_scalar;

    for (int c = tid; c < cnt; c += 256)
        attw[c] = __fdiv_rn(attw[c], denom);
    __syncthreads();

    // 5. AV: two halves of the block split the kept columns
    {
        int d = tid & 127;
        int half = tid >> 7;
        float acc = 0.f;
        const float* vbase = &g_vr[(size_t)kvh * QLEN * HD + d];
        for (int c = half; c < cnt; c += 2)
            acc = __fmaf_rn(attw[c], __ldg(&vbase[(size_t)kept_idx[c] * HD]), acc);
        if (half == 0) obuf[d] = acc;
        __syncthreads();
        if (half == 1)
            g_o[(size_t)p * (NH * HD) + h * HD + d] = __fadd_rn(obuf[d], acc);
    }
}

// ---------------- launch ----------------
extern "C" void kernel_launch(void* const* d_in, const int* in_sizes, int n_in,
                              void* d_out, int out_size)
{
    const float* hidden = (const float*)d_in[0];
    const float* Wq = (const float*)d_in[3];
    const float* Wk = (const float*)d_in[4];
    const float* Wv = (const float*)d_in[5];
    const float* Wo = (const float*)d_in[6];
    const int* sorted_channel = (const int*)d_in[7];
    float* out = (float*)d_out;

    float *qlin, *klin, *vlin, *o;
    cudaGetSymbolAddress((void**)&qlin, g_qlin);
    cudaGetSymbolAddress((void**)&klin, g_klin);
    cudaGetSymbolAddress((void**)&vlin, g_vlin);
    cudaGetSymbolAddress((void**)&o, g_o);

    cudaFuncSetAttribute(gemm_tf32,
                         cudaFuncAttributeMaxDynamicSharedMemorySize, SMEM_BYTES);

    dim3 t256(256);
    // Q, K, V projections fused into one launch (z = 0,1,2; unused CTAs exit)
    gemm_tf32<<<dim3(DMODEL / GBN, QLEN / GBM, 3), t256, SMEM_BYTES>>>(
        hidden,
        Wq, qlin, DMODEL,
        Wk, klin, NKV * HD,
        Wv, vlin, NKV * HD,
        DMODEL);
    rope_kernel<<<dim3(QLEN, NH + 2 * NKV), 128>>>();
    gqk_kernel<<<dim3(QLEN, NH / 8), t256>>>(sorted_channel);
    attn_kernel<<<dim3(QLEN, NH), t256>>>();
    // output projection
    gemm_tf32<<<dim3(DMODEL / GBN, QLEN / GBM, 1), t256, SMEM_BYTES>>>(
        o,
        Wo, out, DMODEL,
        Wo, out, DMODEL,
        Wo, out, DMODEL,
        DMODEL);
}

// round 13
// speedup vs baseline: 1.4010x; 1.0631x over previous
#include <cuda_runtime.h>
#include <math.h>
#include <float.h>

#define QLEN 1024
#define DMODEL 4096
#define NH 32
#define NKV 8
#define HD 128
#define OUTL 16
#define KEEP 256

// ---------------- scratch (static device globals; no allocation) ----------------
__device__ float g_qlin[QLEN * DMODEL];
__device__ float g_klin[QLEN * NKV * HD];
__device__ float g_vlin[QLEN * NKV * HD];
__device__ float g_qr[NH * QLEN * HD];
__device__ float g_kr[NKV * QLEN * HD];
__device__ float g_vr[NKV * QLEN * HD];
__device__ float g_gq[NH * QLEN * OUTL];
__device__ float g_gk[NH * QLEN * OUTL];
__device__ float g_o[QLEN * NH * HD];

// ---------------- 3xTF32 tensor-core GEMM, 3-stage cp.async pipeline ------------
// Consumer math (splits, MMA order, fold cadence) bit-identical to round-7 form.
// A smem: [m][SPITCH] floats (pitch 36). B smem: [k][BPITCH] floats (pitch 72).
#define GBM 128
#define GBN 64
#define GBK 32
#define SPITCH 36
#define BPITCH 72
#define STAGES 3
#define A_TILE_FLOATS (GBM * SPITCH)          // 4608
#define B_TILE_FLOATS (GBK * BPITCH)          // 2304
#define STAGE_FLOATS (A_TILE_FLOATS + B_TILE_FLOATS)
#define SMEM_BYTES (STAGES * STAGE_FLOATS * 4)   // 82944

__device__ __forceinline__ void tf32_split(float x, unsigned& hi, unsigned& lo) {
    unsigned h;
    asm("cvt.rna.tf32.f32 %0, %1;" : "=r"(h) : "f"(x));
    float r = __fadd_rn(x, -__uint_as_float(h));
    unsigned l;
    asm("cvt.rna.tf32.f32 %0, %1;" : "=r"(l) : "f"(r));
    hi = h; lo = l;
}

__device__ __forceinline__ void mma_tf32(float* d, const unsigned* a, const unsigned* b) {
    asm volatile(
        "mma.sync.aligned.m16n8k8.row.col.f32.tf32.tf32.f32 "
        "{%0,%1,%2,%3}, {%4,%5,%6,%7}, {%8,%9}, {%0,%1,%2,%3};"
        : "+f"(d[0]), "+f"(d[1]), "+f"(d[2]), "+f"(d[3])
        : "r"(a[0]), "r"(a[1]), "r"(a[2]), "r"(a[3]), "r"(b[0]), "r"(b[1]));
}

__device__ __forceinline__ void cp16(unsigned smem_addr, const void* gptr) {
    asm volatile("cp.async.ca.shared.global [%0], [%1], 16;"
                 :: "r"(smem_addr), "l"(gptr));
}

__global__ __launch_bounds__(256, 2) void gemm_tf32(
    const float* __restrict__ A,
    const float* __restrict__ B0, float* __restrict__ C0, int N0,
    const float* __restrict__ B1, float* __restrict__ C1, int N1,
    const float* __restrict__ B2, float* __restrict__ C2, int N2,
    int K)
{
    const float* B;
    float* C;
    int N;
    if (blockIdx.z == 0)      { B = B0; C = C0; N = N0; }
    else if (blockIdx.z == 1) { B = B1; C = C1; N = N1; }
    else                      { B = B2; C = C2; N = N2; }
    if ((int)blockIdx.x * GBN >= N) return;

    extern __shared__ float smem_dyn[];
    unsigned smem_base;
    asm("{ .reg .u64 t; cvta.to.shared.u64 t, %1; cvt.u32.u64 %0, t; }"
        : "=r"(smem_base) : "l"(smem_dyn));

    int tid = threadIdx.x;
    int lane = tid & 31;
    int wid = tid >> 5;
    int wm = (wid >> 1) * 32;
    int wn = (wid & 1) * 32;
    int g = lane >> 2;
    int t4 = lane & 3;

    int bm = blockIdx.y * GBM;
    int bn = blockIdx.x * GBN;

    // per-thread cp.async coords
    int arow[4], acol[4];
#pragma unroll
    for (int i = 0; i < 4; ++i) {
        int idx = tid + i * 256;
        arow[i] = idx >> 3;
        acol[i] = (idx & 7) << 2;
    }
    int bkrow[2], bncol[2];
#pragma unroll
    for (int i = 0; i < 2; ++i) {
        int idx = tid + i * 256;
        bkrow[i] = idx >> 4;
        bncol[i] = (idx & 15) << 2;
    }

    int ntiles = K / GBK;

    // issue loads for tile tt into stage s
    auto issue_tile = [&](int tt, int s) {
        int k0 = tt * GBK;
        unsigned abase = smem_base + (unsigned)(s * STAGE_FLOATS) * 4u;
        unsigned bbase = abase + (unsigned)A_TILE_FLOATS * 4u;
#pragma unroll
        for (int i = 0; i < 4; ++i)
            cp16(abase + (unsigned)(arow[i] * SPITCH + acol[i]) * 4u,
                 &A[(size_t)(bm + arow[i]) * K + k0 + acol[i]]);
#pragma unroll
        for (int i = 0; i < 2; ++i)
            cp16(bbase + (unsigned)(bkrow[i] * BPITCH + bncol[i]) * 4u,
                 &B[(size_t)(k0 + bkrow[i]) * N + bn + bncol[i]]);
    };

    float acc[2][4][4], mst[2][4][4];
#pragma unroll
    for (int mt = 0; mt < 2; ++mt)
#pragma unroll
        for (int nt = 0; nt < 4; ++nt)
#pragma unroll
            for (int r = 0; r < 4; ++r) { acc[mt][nt][r] = 0.f; mst[mt][nt][r] = 0.f; }

    // prologue: stages for tiles 0 and 1
    issue_tile(0, 0);
    asm volatile("cp.async.commit_group;");
    if (ntiles > 1) issue_tile(1, 1);
    asm volatile("cp.async.commit_group;");

    for (int t = 0; t < ntiles; ++t) {
        asm volatile("cp.async.wait_group 1;");
        __syncthreads();

        if (t + 2 < ntiles) issue_tile(t + 2, (t + 2) % STAGES);
        asm volatile("cp.async.commit_group;");

        const float* Asf = smem_dyn + (t % STAGES) * STAGE_FLOATS;
        const float* Bsf = Asf + A_TILE_FLOATS;

#pragma unroll
        for (int ks = 0; ks < GBK / 8; ++ks) {
            int kb = ks * 8;
            unsigned ah[2][4], al[2][4];
#pragma unroll
            for (int mt = 0; mt < 2; ++mt) {
                int r0 = wm + mt * 16;
                tf32_split(Asf[(r0 + g) * SPITCH + kb + t4],         ah[mt][0], al[mt][0]);
                tf32_split(Asf[(r0 + g + 8) * SPITCH + kb + t4],     ah[mt][1], al[mt][1]);
                tf32_split(Asf[(r0 + g) * SPITCH + kb + t4 + 4],     ah[mt][2], al[mt][2]);
                tf32_split(Asf[(r0 + g + 8) * SPITCH + kb + t4 + 4], ah[mt][3], al[mt][3]);
            }
            unsigned bh[4][2], bl[4][2];
#pragma unroll
            for (int nt = 0; nt < 4; ++nt) {
                int col = wn + nt * 8 + g;
                tf32_split(Bsf[(kb + t4) * BPITCH + col],     bh[nt][0], bl[nt][0]);
                tf32_split(Bsf[(kb + t4 + 4) * BPITCH + col], bh[nt][1], bl[nt][1]);
            }
#pragma unroll
            for (int mt = 0; mt < 2; ++mt)
#pragma unroll
                for (int nt = 0; nt < 4; ++nt) {
                    mma_tf32(acc[mt][nt], ah[mt], bh[nt]);
                    mma_tf32(acc[mt][nt], al[mt], bh[nt]);
                    mma_tf32(acc[mt][nt], ah[mt], bl[nt]);
                }
        }

        if ((t & 3) == 3) {
#pragma unroll
            for (int mt = 0; mt < 2; ++mt)
#pragma unroll
                for (int nt = 0; nt < 4; ++nt)
#pragma unroll
                    for (int r = 0; r < 4; ++r) {
                        mst[mt][nt][r] = __fadd_rn(mst[mt][nt][r], acc[mt][nt][r]);
                        acc[mt][nt][r] = 0.f;
                    }
        }
    }

#pragma unroll
    for (int mt = 0; mt < 2; ++mt)
#pragma unroll
        for (int nt = 0; nt < 4; ++nt) {
            int r0 = bm + wm + mt * 16 + g;
            int c0 = bn + wn + nt * 8 + t4 * 2;
            *(float2*)&C[(size_t)r0 * N + c0] =
                make_float2(mst[mt][nt][0], mst[mt][nt][1]);
            *(float2*)&C[(size_t)(r0 + 8) * N + c0] =
                make_float2(mst[mt][nt][2], mst[mt][nt][3]);
        }
}

// ---------------- RoPE + layout transpose (precision-matched) ----------------
__global__ void rope_kernel()
{
    int p = blockIdx.x;
    int hh = blockIdx.y;
    int d = threadIdx.x;

    int i = d & 63;
    float P = (float)pow(10000.0, (double)(2 * i) / 128.0);
    float invf = __fdiv_rn(1.0f, P);
    float ang = __fmul_rn((float)p, invf);
    float c = (float)cos((double)ang);
    float s = (float)sin((double)ang);

    if (hh < NH) {
        const float* base = &g_qlin[(size_t)p * DMODEL + hh * HD];
        float v = base[d];
        float other = (d < 64) ? -base[d + 64] : base[d - 64];
        g_qr[((size_t)hh * QLEN + p) * HD + d] =
            __fadd_rn(__fmul_rn(v, c), __fmul_rn(other, s));
    } else if (hh < NH + NKV) {
        int kvh = hh - NH;
        const float* base = &g_klin[(size_t)p * (NKV * HD) + kvh * HD];
        float v = base[d];
        float other = (d < 64) ? -base[d + 64] : base[d - 64];
        g_kr[((size_t)kvh * QLEN + p) * HD + d] =
            __fadd_rn(__fmul_rn(v, c), __fmul_rn(other, s));
    } else {
        int kvh = hh - NH - NKV;
        g_vr[((size_t)kvh * QLEN + p) * HD + d] =
            g_vlin[(size_t)p * (NKV * HD) + kvh * HD + d];
    }
}

// ---------------- label build: 8 warps per block, one (p,h) per warp ------------
__global__ __launch_bounds__(256) void gqk_kernel(const int* __restrict__ sorted_channel)
{
    int warp = threadIdx.x >> 5;
    int lane = threadIdx.x & 31;
    int p = blockIdx.x;
    int h = blockIdx.y * 8 + warp;

    int j = lane & 15;
    bool isK = lane >= 16;

    int ch = sorted_channel[h * HD + j];
    float t;
    if (!isK) t = g_qr[((size_t)h * QLEN + p) * HD + ch];
    else      t = g_kr[((size_t)(h >> 2) * QLEN + p) * HD + ch];

    float mn = t, mx = t;
#pragma unroll
    for (int off = 1; off < 16; off <<= 1) {
        mn = fminf(mn, __shfl_xor_sync(0xffffffffu, mn, off));
        mx = fmaxf(mx, __shfl_xor_sync(0xffffffffu, mx, off));
    }
    float rng = __fadd_rn(mx, -mn);
    if (rng == 0.0f) rng = 1.0f;
    float scale = __fdiv_rn(15.0f, rng);
    float qv = rintf(__fmul_rn(__fadd_rn(t, -mn), scale));
    qv = fminf(fmaxf(qv, 0.0f), 15.0f);
    float outv = __fadd_rn(__fdiv_rn(qv, scale), mn);

    if (!isK) g_gq[((size_t)h * QLEN + p) * OUTL + j] = outv;
    else      g_gk[((size_t)h * QLEN + p) * OUTL + j] = outv;
}

// ---------------- fused gattn -> stable top-256 -> attn -> softmax -> AV ----
__global__ __launch_bounds__(256) void attn_kernel()
{
    int p = blockIdx.x;
    int h = blockIdx.y;
    int kvh = h >> 2;
    int tid = threadIdx.x;
    int lane = tid & 31;
    int warp = tid >> 5;
    unsigned lmask = (1u << lane) - 1u;

    __shared__ float gq_s[OUTL];
    __shared__ float q_s[HD];
    __shared__ unsigned keys[QLEN];
    __shared__ unsigned hist[256];
    __shared__ unsigned wsum[8];
    __shared__ int kept_idx[KEEP];
    __shared__ float attw[KEEP];
    __shared__ float obuf[HD];
    __shared__ unsigned sh_prefix;
    __shared__ int sh_want;
    __shared__ int wcnt[8];
    __shared__ int wcnt2[8];
    __shared__ int eqbase_s;
    __shared__ int kbase_s;
    __shared__ float red[8];
    __shared__ float sh_scalar;

    if (tid < OUTL) gq_s[tid] = g_gq[((size_t)h * QLEN + p) * OUTL + tid];
    if (tid < HD)   q_s[tid] = g_qr[((size_t)h * QLEN + p) * HD + tid];
    if (tid == 0) { eqbase_s = 0; kbase_s = 0; }
    __syncthreads();

    int nvalid = p + 1;

    // 1. gattn keys: strict ascending sequential FMA chain, exact /4.
    for (int j = tid; j < nvalid; j += 256) {
        const float* g = &g_gk[((size_t)h * QLEN + j) * OUTL];
        float s = __fmul_rn(g[0], gq_s[0]);
#pragma unroll
        for (int d = 1; d < OUTL; ++d)
            s = __fmaf_rn(g[d], gq_s[d], s);
        s = __fmul_rn(s, 0.25f);
        unsigned u = __float_as_uint(s);
        if ((u << 1) == 0u) u = 0u;
        u ^= (u & 0x80000000u) ? 0xFFFFFFFFu : 0x80000000u;
        keys[j] = u;
    }
    __syncthreads();

    // 2. stable top-KEEP selection (radix threshold + ordered compaction)
    int cnt;
    if (nvalid <= KEEP) {
        for (int j = tid; j < nvalid; j += 256) kept_idx[j] = j;
        cnt = nvalid;
        __syncthreads();
    } else {
        unsigned prefix = 0;
        int want = KEEP;
        for (int byte = 3; byte >= 0; --byte) {
            hist[tid] = 0;
            __syncthreads();
            int shift = byte * 8;
            unsigned pmask = (byte == 3) ? 0u : (0xFFFFFFFFu << (shift + 8));
            for (int j = tid; j < nvalid; j += 256) {
                unsigned u = keys[j];
                if ((u & pmask) == prefix)
                    atomicAdd(&hist[(u >> shift) & 255u], 1u);
            }
            __syncthreads();

            unsigned hv = hist[tid];
            unsigned s = hv;
#pragma unroll
            for (int off = 1; off < 32; off <<= 1) {
                unsigned t2 = __shfl_down_sync(0xffffffffu, s, off);
                if (lane + off < 32) s += t2;
            }
            if (lane == 0) wsum[warp] = s;
            __syncthreads();
            unsigned add = 0;
#pragma unroll
            for (int w = 0; w < 8; ++w)
                if (w > warp) add += wsum[w];
            unsigned suft = s + add;
            unsigned above = suft - hv;
            if (suft >= (unsigned)want && above < (unsigned)want) {
                sh_prefix = prefix | ((unsigned)tid << shift);
                sh_want = want - (int)above;
            }
            __syncthreads();
            prefix = sh_prefix;
            want = sh_want;
            __syncthreads();
        }
        unsigned uT = prefix;
        int r = want;

        // ordered stable compaction: chunks asc, warps asc, lanes asc
#pragma unroll
        for (int chunk = 0; chunk < QLEN / 256; ++chunk) {
            int j = chunk * 256 + tid;
            bool isval = j < nvalid;
            unsigned u = isval ? keys[j] : 0u;
            bool gt = isval && (u > uT);
            bool eq = isval && (u == uT);

            unsigned bal_eq = __ballot_sync(0xffffffffu, eq);
            if (lane == 0) wcnt[warp] = __popc(bal_eq);
            __syncthreads();
            int eqoff = eqbase_s;
            for (int w = 0; w < warp; ++w) eqoff += wcnt[w];
            int eqrank = eqoff + __popc(bal_eq & lmask);
            bool keep = gt || (eq && eqrank < r);

            unsigned bal_k = __ballot_sync(0xffffffffu, keep);
            if (lane == 0) wcnt2[warp] = __popc(bal_k);
            __syncthreads();
            int koff = kbase_s;
            for (int w = 0; w < warp; ++w) koff += wcnt2[w];
            if (keep) kept_idx[koff + __popc(bal_k & lmask)] = j;
            __syncthreads();
            if (tid == 0) {
                int te = 0, tk = 0;
                for (int w = 0; w < 8; ++w) { te += wcnt[w]; tk += wcnt2[w]; }
                eqbase_s += te;
                kbase_s += tk;
            }
            __syncthreads();
        }
        cnt = kbase_s;
    }
    __syncthreads();

    // 3. attn scores on kept columns (warp per column, float4 loads)
    {
        float4 qreg = *(const float4*)&q_s[lane * 4];
        for (int c = warp; c < cnt; c += 8) {
            int j = kept_idx[c];
            float4 kv = *(const float4*)&g_kr[((size_t)kvh * QLEN + j) * HD + lane * 4];
            float s = __fmul_rn(qreg.x, kv.x);
            s = __fmaf_rn(qreg.y, kv.y, s);
            s = __fmaf_rn(qreg.z, kv.z, s);
            s = __fmaf_rn(qreg.w, kv.w, s);
#pragma unroll
            for (int off = 16; off; off >>= 1) s += __shfl_xor_sync(0xffffffffu, s, off);
            if (lane == 0) attw[c] = s / 11.313708498984761f;
        }
    }
    __syncthreads();

    // 4. softmax over kept (expf: post-selection, ulp noise only)
    float vmax = -FLT_MAX;
    for (int c = tid; c < cnt; c += 256) vmax = fmaxf(vmax, attw[c]);
#pragma unroll
    for (int off = 16; off; off >>= 1)
        vmax = fmaxf(vmax, __shfl_xor_sync(0xffffffffu, vmax, off));
    if (lane == 0) red[warp] = vmax;
    __syncthreads();
    if (warp == 0) {
        float m = (lane < 8) ? red[lane] : -FLT_MAX;
#pragma unroll
        for (int off = 4; off; off >>= 1)
            m = fmaxf(m, __shfl_xor_sync(0xffffffffu, m, off));
        if (lane == 0) sh_scalar = m;
    }
    __syncthreads();
    float M = sh_scalar;

    float lsum = 0.f;
    for (int c = tid; c < cnt; c += 256) {
        float e = expf(__fadd_rn(attw[c], -M));
        attw[c] = e;
        lsum += e;
    }
#pragma unroll
    for (int off = 16; off; off >>= 1)
        lsum += __shfl_xor_sync(0xffffffffu, lsum, off);
    if (lane == 0) red[warp] = lsum;
    __syncthreads();
    if (warp == 0) {
        float s2 = (lane < 8) ? red[lane] : 0.f;
#pragma unroll
        for (int off = 4; off; off >>= 1)
            s2 += __shfl_xor_sync(0xffffffffu, s2, off);
        if (lane == 0) sh_scalar = s2;
    }
    __syncthreads();
    float denom = sh_scalar;

    for (int c = tid; c < cnt; c += 256)
        attw[c] = __fdiv_rn(attw[c], denom);
    __syncthreads();

    // 5. AV: two halves of the block split the kept columns
    {
        int d = tid & 127;
        int half = tid >> 7;
        float acc = 0.f;
        const float* vbase = &g_vr[(size_t)kvh * QLEN * HD + d];
        for (int c = half; c < cnt; c += 2)
            acc = __fmaf_rn(attw[c], __ldg(&vbase[(size_t)kept_idx[c] * HD]), acc);
        if (half == 0) obuf[d] = acc;
        __syncthreads();
        if (half == 1)
            g_o[(size_t)p * (NH * HD) + h * HD + d] = __fadd_rn(obuf[d], acc);
    }
}

// ---------------- launch ----------------
extern "C" void kernel_launch(void* const* d_in, const int* in_sizes, int n_in,
                              void* d_out, int out_size)
{
    const float* hidden = (const float*)d_in[0];
    const float* Wq = (const float*)d_in[3];
    const float* Wk = (const float*)d_in[4];
    const float* Wv = (const float*)d_in[5];
    const float* Wo = (const float*)d_in[6];
    const int* sorted_channel = (const int*)d_in[7];
    float* out = (float*)d_out;

    float *qlin, *klin, *vlin, *o;
    cudaGetSymbolAddress((void**)&qlin, g_qlin);
    cudaGetSymbolAddress((void**)&klin, g_klin);
    cudaGetSymbolAddress((void**)&vlin, g_vlin);
    cudaGetSymbolAddress((void**)&o, g_o);

    cudaFuncSetAttribute(gemm_tf32,
                         cudaFuncAttributeMaxDynamicSharedMemorySize, SMEM_BYTES);

    dim3 t256(256);
    // Q, K, V projections fused into one launch (z = 0,1,2; unused CTAs exit)
    gemm_tf32<<<dim3(DMODEL / GBN, QLEN / GBM, 3), t256, SMEM_BYTES>>>(
        hidden,
        Wq, qlin, DMODEL,
        Wk, klin, NKV * HD,
        Wv, vlin, NKV * HD,
        DMODEL);
    rope_kernel<<<dim3(QLEN, NH + 2 * NKV), 128>>>();
    gqk_kernel<<<dim3(QLEN, NH / 8), t256>>>(sorted_channel);
    attn_kernel<<<dim3(QLEN, NH), t256>>>();
    // output projection
    gemm_tf32<<<dim3(DMODEL / GBN, QLEN / GBM, 1), t256, SMEM_BYTES>>>(
        o,
        Wo, out, DMODEL,
        Wo, out, DMODEL,
        Wo, out, DMODEL,
        DMODEL);
}

// round 14
// speedup vs baseline: 1.5231x; 1.0872x over previous
#include <cuda_runtime.h>
#include <math.h>
#include <float.h>

#define QLEN 1024
#define DMODEL 4096
#define NH 32
#define NKV 8
#define HD 128
#define OUTL 16
#define KEEP 256

// ---------------- scratch (static device globals; no allocation) ----------------
__device__ float g_qlin[QLEN * DMODEL];
__device__ float g_klin[QLEN * NKV * HD];
__device__ float g_vlin[QLEN * NKV * HD];
__device__ float g_qr[NH * QLEN * HD];
__device__ float g_kr[NKV * QLEN * HD];
__device__ float g_vr[NKV * QLEN * HD];
__device__ float g_gq[NH * QLEN * OUTL];
__device__ float g_gk[NH * QLEN * OUTL];
__device__ float g_o[QLEN * NH * HD];

// ---------------- 3xTF32 tensor-core GEMM, 3-stage cp.async pipeline ------------
// Consumer math (splits, MMA order, fold cadence) bit-identical to round-7 form.
#define GBM 128
#define GBN 64
#define GBK 32
#define SPITCH 36
#define BPITCH 72
#define STAGES 3
#define A_TILE_FLOATS (GBM * SPITCH)
#define B_TILE_FLOATS (GBK * BPITCH)
#define STAGE_FLOATS (A_TILE_FLOATS + B_TILE_FLOATS)
#define SMEM_BYTES (STAGES * STAGE_FLOATS * 4)

__device__ __forceinline__ void tf32_split(float x, unsigned& hi, unsigned& lo) {
    unsigned h;
    asm("cvt.rna.tf32.f32 %0, %1;" : "=r"(h) : "f"(x));
    float r = __fadd_rn(x, -__uint_as_float(h));
    unsigned l;
    asm("cvt.rna.tf32.f32 %0, %1;" : "=r"(l) : "f"(r));
    hi = h; lo = l;
}

__device__ __forceinline__ void mma_tf32(float* d, const unsigned* a, const unsigned* b) {
    asm volatile(
        "mma.sync.aligned.m16n8k8.row.col.f32.tf32.tf32.f32 "
        "{%0,%1,%2,%3}, {%4,%5,%6,%7}, {%8,%9}, {%0,%1,%2,%3};"
        : "+f"(d[0]), "+f"(d[1]), "+f"(d[2]), "+f"(d[3])
        : "r"(a[0]), "r"(a[1]), "r"(a[2]), "r"(a[3]), "r"(b[0]), "r"(b[1]));
}

__device__ __forceinline__ void cp16(unsigned smem_addr, const void* gptr) {
    asm volatile("cp.async.ca.shared.global [%0], [%1], 16;"
                 :: "r"(smem_addr), "l"(gptr));
}

__global__ __launch_bounds__(256, 2) void gemm_tf32(
    const float* __restrict__ A,
    const float* __restrict__ B0, float* __restrict__ C0, int N0,
    const float* __restrict__ B1, float* __restrict__ C1, int N1,
    const float* __restrict__ B2, float* __restrict__ C2, int N2,
    int K)
{
    const float* B;
    float* C;
    int N;
    if (blockIdx.z == 0)      { B = B0; C = C0; N = N0; }
    else if (blockIdx.z == 1) { B = B1; C = C1; N = N1; }
    else                      { B = B2; C = C2; N = N2; }
    if ((int)blockIdx.x * GBN >= N) return;

    extern __shared__ float smem_dyn[];
    unsigned smem_base;
    asm("{ .reg .u64 t; cvta.to.shared.u64 t, %1; cvt.u32.u64 %0, t; }"
        : "=r"(smem_base) : "l"(smem_dyn));

    int tid = threadIdx.x;
    int lane = tid & 31;
    int wid = tid >> 5;
    int wm = (wid >> 1) * 32;
    int wn = (wid & 1) * 32;
    int g = lane >> 2;
    int t4 = lane & 3;

    int bm = blockIdx.y * GBM;
    int bn = blockIdx.x * GBN;

    int arow[4], acol[4];
#pragma unroll
    for (int i = 0; i < 4; ++i) {
        int idx = tid + i * 256;
        arow[i] = idx >> 3;
        acol[i] = (idx & 7) << 2;
    }
    int bkrow[2], bncol[2];
#pragma unroll
    for (int i = 0; i < 2; ++i) {
        int idx = tid + i * 256;
        bkrow[i] = idx >> 4;
        bncol[i] = (idx & 15) << 2;
    }

    int ntiles = K / GBK;

    auto issue_tile = [&](int tt, int s) {
        int k0 = tt * GBK;
        unsigned abase = smem_base + (unsigned)(s * STAGE_FLOATS) * 4u;
        unsigned bbase = abase + (unsigned)A_TILE_FLOATS * 4u;
#pragma unroll
        for (int i = 0; i < 4; ++i)
            cp16(abase + (unsigned)(arow[i] * SPITCH + acol[i]) * 4u,
                 &A[(size_t)(bm + arow[i]) * K + k0 + acol[i]]);
#pragma unroll
        for (int i = 0; i < 2; ++i)
            cp16(bbase + (unsigned)(bkrow[i] * BPITCH + bncol[i]) * 4u,
                 &B[(size_t)(k0 + bkrow[i]) * N + bn + bncol[i]]);
    };

    float acc[2][4][4], mst[2][4][4];
#pragma unroll
    for (int mt = 0; mt < 2; ++mt)
#pragma unroll
        for (int nt = 0; nt < 4; ++nt)
#pragma unroll
            for (int r = 0; r < 4; ++r) { acc[mt][nt][r] = 0.f; mst[mt][nt][r] = 0.f; }

    issue_tile(0, 0);
    asm volatile("cp.async.commit_group;");
    if (ntiles > 1) issue_tile(1, 1);
    asm volatile("cp.async.commit_group;");

    for (int t = 0; t < ntiles; ++t) {
        asm volatile("cp.async.wait_group 1;");
        __syncthreads();

        if (t + 2 < ntiles) issue_tile(t + 2, (t + 2) % STAGES);
        asm volatile("cp.async.commit_group;");

        const float* Asf = smem_dyn + (t % STAGES) * STAGE_FLOATS;
        const float* Bsf = Asf + A_TILE_FLOATS;

#pragma unroll
        for (int ks = 0; ks < GBK / 8; ++ks) {
            int kb = ks * 8;
            unsigned ah[2][4], al[2][4];
#pragma unroll
            for (int mt = 0; mt < 2; ++mt) {
                int r0 = wm + mt * 16;
                tf32_split(Asf[(r0 + g) * SPITCH + kb + t4],         ah[mt][0], al[mt][0]);
                tf32_split(Asf[(r0 + g + 8) * SPITCH + kb + t4],     ah[mt][1], al[mt][1]);
                tf32_split(Asf[(r0 + g) * SPITCH + kb + t4 + 4],     ah[mt][2], al[mt][2]);
                tf32_split(Asf[(r0 + g + 8) * SPITCH + kb + t4 + 4], ah[mt][3], al[mt][3]);
            }
            unsigned bh[4][2], bl[4][2];
#pragma unroll
            for (int nt = 0; nt < 4; ++nt) {
                int col = wn + nt * 8 + g;
                tf32_split(Bsf[(kb + t4) * BPITCH + col],     bh[nt][0], bl[nt][0]);
                tf32_split(Bsf[(kb + t4 + 4) * BPITCH + col], bh[nt][1], bl[nt][1]);
            }
#pragma unroll
            for (int mt = 0; mt < 2; ++mt)
#pragma unroll
                for (int nt = 0; nt < 4; ++nt) {
                    mma_tf32(acc[mt][nt], ah[mt], bh[nt]);
                    mma_tf32(acc[mt][nt], al[mt], bh[nt]);
                    mma_tf32(acc[mt][nt], ah[mt], bl[nt]);
                }
        }

        if ((t & 3) == 3) {
#pragma unroll
            for (int mt = 0; mt < 2; ++mt)
#pragma unroll
                for (int nt = 0; nt < 4; ++nt)
#pragma unroll
                    for (int r = 0; r < 4; ++r) {
                        mst[mt][nt][r] = __fadd_rn(mst[mt][nt][r], acc[mt][nt][r]);
                        acc[mt][nt][r] = 0.f;
                    }
        }
    }

#pragma unroll
    for (int mt = 0; mt < 2; ++mt)
#pragma unroll
        for (int nt = 0; nt < 4; ++nt) {
            int r0 = bm + wm + mt * 16 + g;
            int c0 = bn + wn + nt * 8 + t4 * 2;
            *(float2*)&C[(size_t)r0 * N + c0] =
                make_float2(mst[mt][nt][0], mst[mt][nt][1]);
            *(float2*)&C[(size_t)(r0 + 8) * N + c0] =
                make_float2(mst[mt][nt][2], mst[mt][nt][3]);
        }
}

// ---------------- RoPE + layout transpose (precision-matched) ----------------
__global__ void rope_kernel()
{
    int p = blockIdx.x;
    int hh = blockIdx.y;
    int d = threadIdx.x;

    int i = d & 63;
    float P = (float)pow(10000.0, (double)(2 * i) / 128.0);
    float invf = __fdiv_rn(1.0f, P);
    float ang = __fmul_rn((float)p, invf);
    float c = (float)cos((double)ang);
    float s = (float)sin((double)ang);

    if (hh < NH) {
        const float* base = &g_qlin[(size_t)p * DMODEL + hh * HD];
        float v = base[d];
        float other = (d < 64) ? -base[d + 64] : base[d - 64];
        g_qr[((size_t)hh * QLEN + p) * HD + d] =
            __fadd_rn(__fmul_rn(v, c), __fmul_rn(other, s));
    } else if (hh < NH + NKV) {
        int kvh = hh - NH;
        const float* base = &g_klin[(size_t)p * (NKV * HD) + kvh * HD];
        float v = base[d];
        float other = (d < 64) ? -base[d + 64] : base[d - 64];
        g_kr[((size_t)kvh * QLEN + p) * HD + d] =
            __fadd_rn(__fmul_rn(v, c), __fmul_rn(other, s));
    } else {
        int kvh = hh - NH - NKV;
        g_vr[((size_t)kvh * QLEN + p) * HD + d] =
            g_vlin[(size_t)p * (NKV * HD) + kvh * HD + d];
    }
}

// ---------------- label build: 8 warps per block, one (p,h) per warp ------------
__global__ __launch_bounds__(256) void gqk_kernel(const int* __restrict__ sorted_channel)
{
    int warp = threadIdx.x >> 5;
    int lane = threadIdx.x & 31;
    int p = blockIdx.x;
    int h = blockIdx.y * 8 + warp;

    int j = lane & 15;
    bool isK = lane >= 16;

    int ch = sorted_channel[h * HD + j];
    float t;
    if (!isK) t = g_qr[((size_t)h * QLEN + p) * HD + ch];
    else      t = g_kr[((size_t)(h >> 2) * QLEN + p) * HD + ch];

    float mn = t, mx = t;
#pragma unroll
    for (int off = 1; off < 16; off <<= 1) {
        mn = fminf(mn, __shfl_xor_sync(0xffffffffu, mn, off));
        mx = fmaxf(mx, __shfl_xor_sync(0xffffffffu, mx, off));
    }
    float rng = __fadd_rn(mx, -mn);
    if (rng == 0.0f) rng = 1.0f;
    float scale = __fdiv_rn(15.0f, rng);
    float qv = rintf(__fmul_rn(__fadd_rn(t, -mn), scale));
    qv = fminf(fmaxf(qv, 0.0f), 15.0f);
    float outv = __fadd_rn(__fdiv_rn(qv, scale), mn);

    if (!isK) g_gq[((size_t)h * QLEN + p) * OUTL + j] = outv;
    else      g_gk[((size_t)h * QLEN + p) * OUTL + j] = outv;
}

// ---------------- fused gattn -> stable top-256 -> attn -> softmax -> AV --------
// Keys live in registers (4 per thread); key-gen uses float4 loads with the
// identical ascending FMA order -> selection bit-identical to prior rounds.
__global__ __launch_bounds__(256) void attn_kernel()
{
    int p = blockIdx.x;
    int h = blockIdx.y;
    int kvh = h >> 2;
    int tid = threadIdx.x;
    int lane = tid & 31;
    int warp = tid >> 5;
    unsigned lmask = (1u << lane) - 1u;

    __shared__ float gq_s[OUTL];
    __shared__ float q_s[HD];
    __shared__ unsigned hist[256];
    __shared__ unsigned wsum[8];
    __shared__ int kept_idx[KEEP];
    __shared__ float attw[KEEP];
    __shared__ float obuf[HD];
    __shared__ unsigned sh_prefix;
    __shared__ int sh_want;
    __shared__ int wcnt[8];
    __shared__ int wcnt2[8];
    __shared__ int eqbase_s;
    __shared__ int kbase_s;
    __shared__ float red[8];
    __shared__ float sh_scalar;

    if (tid < OUTL) gq_s[tid] = g_gq[((size_t)h * QLEN + p) * OUTL + tid];
    if (tid < HD)   q_s[tid] = g_qr[((size_t)h * QLEN + p) * HD + tid];
    if (tid == 0) { eqbase_s = 0; kbase_s = 0; }
    __syncthreads();

    int nvalid = p + 1;

    // 1. gattn keys -> registers. float4 loads; FMA order d=0..15 ascending
    //    (identical arithmetic to the scalar chain), exact /4, -0 canon.
    unsigned mykey[4];
#pragma unroll
    for (int chunk = 0; chunk < 4; ++chunk) {
        int j = chunk * 256 + tid;
        unsigned u = 0u;
        if (j < nvalid) {
            const float4* g4 = (const float4*)&g_gk[((size_t)h * QLEN + j) * OUTL];
            float4 a = g4[0], b = g4[1], c4 = g4[2], e = g4[3];
            float s = __fmul_rn(a.x, gq_s[0]);
            s = __fmaf_rn(a.y, gq_s[1], s);
            s = __fmaf_rn(a.z, gq_s[2], s);
            s = __fmaf_rn(a.w, gq_s[3], s);
            s = __fmaf_rn(b.x, gq_s[4], s);
            s = __fmaf_rn(b.y, gq_s[5], s);
            s = __fmaf_rn(b.z, gq_s[6], s);
            s = __fmaf_rn(b.w, gq_s[7], s);
            s = __fmaf_rn(c4.x, gq_s[8], s);
            s = __fmaf_rn(c4.y, gq_s[9], s);
            s = __fmaf_rn(c4.z, gq_s[10], s);
            s = __fmaf_rn(c4.w, gq_s[11], s);
            s = __fmaf_rn(e.x, gq_s[12], s);
            s = __fmaf_rn(e.y, gq_s[13], s);
            s = __fmaf_rn(e.z, gq_s[14], s);
            s = __fmaf_rn(e.w, gq_s[15], s);
            s = __fmul_rn(s, 0.25f);
            u = __float_as_uint(s);
            if ((u << 1) == 0u) u = 0u;
            u ^= (u & 0x80000000u) ? 0xFFFFFFFFu : 0x80000000u;
        }
        mykey[chunk] = u;
    }
    __syncthreads();

    // 2. stable top-KEEP selection (radix threshold + ordered compaction)
    int cnt;
    if (nvalid <= KEEP) {
        for (int j = tid; j < nvalid; j += 256) kept_idx[j] = j;
        cnt = nvalid;
        __syncthreads();
    } else {
        unsigned prefix = 0;
        int want = KEEP;
        for (int byte = 3; byte >= 0; --byte) {
            hist[tid] = 0;
            __syncthreads();
            int shift = byte * 8;
            unsigned pmask = (byte == 3) ? 0u : (0xFFFFFFFFu << (shift + 8));
#pragma unroll
            for (int chunk = 0; chunk < 4; ++chunk) {
                int j = chunk * 256 + tid;
                unsigned u = mykey[chunk];
                if (j < nvalid && (u & pmask) == prefix)
                    atomicAdd(&hist[(u >> shift) & 255u], 1u);
            }
            __syncthreads();

            unsigned hv = hist[tid];
            unsigned s = hv;
#pragma unroll
            for (int off = 1; off < 32; off <<= 1) {
                unsigned t2 = __shfl_down_sync(0xffffffffu, s, off);
                if (lane + off < 32) s += t2;
            }
            if (lane == 0) wsum[warp] = s;
            __syncthreads();
            unsigned add = 0;
#pragma unroll
            for (int w = 0; w < 8; ++w)
                if (w > warp) add += wsum[w];
            unsigned suft = s + add;
            unsigned above = suft - hv;
            if (suft >= (unsigned)want && above < (unsigned)want) {
                sh_prefix = prefix | ((unsigned)tid << shift);
                sh_want = want - (int)above;
            }
            __syncthreads();
            prefix = sh_prefix;
            want = sh_want;
            __syncthreads();
        }
        unsigned uT = prefix;
        int r = want;

        // ordered stable compaction: chunks asc, warps asc, lanes asc
#pragma unroll
        for (int chunk = 0; chunk < 4; ++chunk) {
            int j = chunk * 256 + tid;
            bool isval = j < nvalid;
            unsigned u = mykey[chunk];
            bool gt = isval && (u > uT);
            bool eq = isval && (u == uT);

            unsigned bal_eq = __ballot_sync(0xffffffffu, eq);
            if (lane == 0) wcnt[warp] = __popc(bal_eq);
            __syncthreads();
            int eqoff = eqbase_s;
            for (int w = 0; w < warp; ++w) eqoff += wcnt[w];
            int eqrank = eqoff + __popc(bal_eq & lmask);
            bool keep = gt || (eq && eqrank < r);

            unsigned bal_k = __ballot_sync(0xffffffffu, keep);
            if (lane == 0) wcnt2[warp] = __popc(bal_k);
            __syncthreads();
            int koff = kbase_s;
            for (int w = 0; w < warp; ++w) koff += wcnt2[w];
            if (keep) kept_idx[koff + __popc(bal_k & lmask)] = j;
            __syncthreads();
            if (tid == 0) {
                int te = 0, tk = 0;
                for (int w = 0; w < 8; ++w) { te += wcnt[w]; tk += wcnt2[w]; }
                eqbase_s += te;
                kbase_s += tk;
            }
            __syncthreads();
        }
        cnt = kbase_s;
    }
    __syncthreads();

    // 3. attn scores on kept columns (warp per column, float4 loads)
    {
        float4 qreg = *(const float4*)&q_s[lane * 4];
        for (int c = warp; c < cnt; c += 8) {
            int j = kept_idx[c];
            float4 kv = *(const float4*)&g_kr[((size_t)kvh * QLEN + j) * HD + lane * 4];
            float s = __fmul_rn(qreg.x, kv.x);
            s = __fmaf_rn(qreg.y, kv.y, s);
            s = __fmaf_rn(qreg.z, kv.z, s);
            s = __fmaf_rn(qreg.w, kv.w, s);
#pragma unroll
            for (int off = 16; off; off >>= 1) s += __shfl_xor_sync(0xffffffffu, s, off);
            if (lane == 0) attw[c] = s / 11.313708498984761f;
        }
    }
    __syncthreads();

    // 4. softmax over kept
    float vmax = -FLT_MAX;
    for (int c = tid; c < cnt; c += 256) vmax = fmaxf(vmax, attw[c]);
#pragma unroll
    for (int off = 16; off; off >>= 1)
        vmax = fmaxf(vmax, __shfl_xor_sync(0xffffffffu, vmax, off));
    if (lane == 0) red[warp] = vmax;
    __syncthreads();
    if (warp == 0) {
        float m = (lane < 8) ? red[lane] : -FLT_MAX;
#pragma unroll
        for (int off = 4; off; off >>= 1)
            m = fmaxf(m, __shfl_xor_sync(0xffffffffu, m, off));
        if (lane == 0) sh_scalar = m;
    }
    __syncthreads();
    float M = sh_scalar;

    float lsum = 0.f;
    for (int c = tid; c < cnt; c += 256) {
        float e = expf(__fadd_rn(attw[c], -M));
        attw[c] = e;
        lsum += e;
    }
#pragma unroll
    for (int off = 16; off; off >>= 1)
        lsum += __shfl_xor_sync(0xffffffffu, lsum, off);
    if (lane == 0) red[warp] = lsum;
    __syncthreads();
    if (warp == 0) {
        float s2 = (lane < 8) ? red[lane] : 0.f;
#pragma unroll
        for (int off = 4; off; off >>= 1)
            s2 += __shfl_xor_sync(0xffffffffu, s2, off);
        if (lane == 0) sh_scalar = s2;
    }
    __syncthreads();
    float denom = sh_scalar;

    for (int c = tid; c < cnt; c += 256)
        attw[c] = __fdiv_rn(attw[c], denom);
    __syncthreads();

    // 5. AV: two halves of the block split the kept columns
    {
        int d = tid & 127;
        int half = tid >> 7;
        float acc = 0.f;
        const float* vbase = &g_vr[(size_t)kvh * QLEN * HD + d];
        for (int c = half; c < cnt; c += 2)
            acc = __fmaf_rn(attw[c], __ldg(&vbase[(size_t)kept_idx[c] * HD]), acc);
        if (half == 0) obuf[d] = acc;
        __syncthreads();
        if (half == 1)
            g_o[(size_t)p * (NH * HD) + h * HD + d] = __fadd_rn(obuf[d], acc);
    }
}

// ---------------- launch ----------------
extern "C" void kernel_launch(void* const* d_in, const int* in_sizes, int n_in,
                              void* d_out, int out_size)
{
    const float* hidden = (const float*)d_in[0];
    const float* Wq = (const float*)d_in[3];
    const float* Wk = (const float*)d_in[4];
    const float* Wv = (const float*)d_in[5];
    const float* Wo = (const float*)d_in[6];
    const int* sorted_channel = (const int*)d_in[7];
    float* out = (float*)d_out;

    float *qlin, *klin, *vlin, *o;
    cudaGetSymbolAddress((void**)&qlin, g_qlin);
    cudaGetSymbolAddress((void**)&klin, g_klin);
    cudaGetSymbolAddress((void**)&vlin, g_vlin);
    cudaGetSymbolAddress((void**)&o, g_o);

    cudaFuncSetAttribute(gemm_tf32,
                         cudaFuncAttributeMaxDynamicSharedMemorySize, SMEM_BYTES);

    dim3 t256(256);
    gemm_tf32<<<dim3(DMODEL / GBN, QLEN / GBM, 3), t256, SMEM_BYTES>>>(
        hidden,
        Wq, qlin, DMODEL,
        Wk, klin, NKV * HD,
        Wv, vlin, NKV * HD,
        DMODEL);
    rope_kernel<<<dim3(QLEN, NH + 2 * NKV), 128>>>();
    gqk_kernel<<<dim3(QLEN, NH / 8), t256>>>(sorted_channel);
    attn_kernel<<<dim3(QLEN, NH), t256>>>();
    gemm_tf32<<<dim3(DMODEL / GBN, QLEN / GBM, 1), t256, SMEM_BYTES>>>(
        o,
        Wo, out, DMODEL,
        Wo, out, DMODEL,
        Wo, out, DMODEL,
        DMODEL);
}

// round 15
// speedup vs baseline: 1.5407x; 1.0116x over previous
#include <cuda_runtime.h>
#include <math.h>
#include <float.h>

#define QLEN 1024
#define DMODEL 4096
#define NH 32
#define NKV 8
#define HD 128
#define OUTL 16
#define KEEP 256

// ---------------- scratch (static device globals; no allocation) ----------------
__device__ float g_qlin[QLEN * DMODEL];
__device__ float g_klin[QLEN * NKV * HD];
__device__ float g_vlin[QLEN * NKV * HD];
__device__ float g_qr[NH * QLEN * HD];
__device__ float g_kr[NKV * QLEN * HD];
__device__ float g_vr[NKV * QLEN * HD];
__device__ float g_gq[NH * QLEN * OUTL];
__device__ float g_gk[NH * QLEN * OUTL];
__device__ float g_o[QLEN * NH * HD];

// ---------------- 3xTF32 tensor-core GEMM, 4-stage cp.async pipeline ------------
// Consumer math (splits, MMA order, fold cadence) bit-identical to round-7 form.
#define GBM 128
#define GBN 64
#define GBK 32
#define SPITCH 36
#define BPITCH 72
#define STAGES 4
#define A_TILE_FLOATS (GBM * SPITCH)
#define B_TILE_FLOATS (GBK * BPITCH)
#define STAGE_FLOATS (A_TILE_FLOATS + B_TILE_FLOATS)
#define SMEM_BYTES (STAGES * STAGE_FLOATS * 4)

__device__ __forceinline__ void tf32_split(float x, unsigned& hi, unsigned& lo) {
    unsigned h;
    asm("cvt.rna.tf32.f32 %0, %1;" : "=r"(h) : "f"(x));
    float r = __fadd_rn(x, -__uint_as_float(h));
    unsigned l;
    asm("cvt.rna.tf32.f32 %0, %1;" : "=r"(l) : "f"(r));
    hi = h; lo = l;
}

__device__ __forceinline__ void mma_tf32(float* d, const unsigned* a, const unsigned* b) {
    asm volatile(
        "mma.sync.aligned.m16n8k8.row.col.f32.tf32.tf32.f32 "
        "{%0,%1,%2,%3}, {%4,%5,%6,%7}, {%8,%9}, {%0,%1,%2,%3};"
        : "+f"(d[0]), "+f"(d[1]), "+f"(d[2]), "+f"(d[3])
        : "r"(a[0]), "r"(a[1]), "r"(a[2]), "r"(a[3]), "r"(b[0]), "r"(b[1]));
}

__device__ __forceinline__ void cp16(unsigned smem_addr, const void* gptr) {
    asm volatile("cp.async.ca.shared.global [%0], [%1], 16;"
                 :: "r"(smem_addr), "l"(gptr));
}

__global__ __launch_bounds__(256, 2) void gemm_tf32(
    const float* __restrict__ A,
    const float* __restrict__ B0, float* __restrict__ C0, int N0,
    const float* __restrict__ B1, float* __restrict__ C1, int N1,
    const float* __restrict__ B2, float* __restrict__ C2, int N2,
    int K)
{
    const float* B;
    float* C;
    int N;
    if (blockIdx.z == 0)      { B = B0; C = C0; N = N0; }
    else if (blockIdx.z == 1) { B = B1; C = C1; N = N1; }
    else                      { B = B2; C = C2; N = N2; }
    if ((int)blockIdx.x * GBN >= N) return;

    extern __shared__ float smem_dyn[];
    unsigned smem_base;
    asm("{ .reg .u64 t; cvta.to.shared.u64 t, %1; cvt.u32.u64 %0, t; }"
        : "=r"(smem_base) : "l"(smem_dyn));

    int tid = threadIdx.x;
    int lane = tid & 31;
    int wid = tid >> 5;
    int wm = (wid >> 1) * 32;
    int wn = (wid & 1) * 32;
    int g = lane >> 2;
    int t4 = lane & 3;

    int bm = blockIdx.y * GBM;
    int bn = blockIdx.x * GBN;

    int arow[4], acol[4];
#pragma unroll
    for (int i = 0; i < 4; ++i) {
        int idx = tid + i * 256;
        arow[i] = idx >> 3;
        acol[i] = (idx & 7) << 2;
    }
    int bkrow[2], bncol[2];
#pragma unroll
    for (int i = 0; i < 2; ++i) {
        int idx = tid + i * 256;
        bkrow[i] = idx >> 4;
        bncol[i] = (idx & 15) << 2;
    }

    int ntiles = K / GBK;

    auto issue_tile = [&](int tt, int s) {
        int k0 = tt * GBK;
        unsigned abase = smem_base + (unsigned)(s * STAGE_FLOATS) * 4u;
        unsigned bbase = abase + (unsigned)A_TILE_FLOATS * 4u;
#pragma unroll
        for (int i = 0; i < 4; ++i)
            cp16(abase + (unsigned)(arow[i] * SPITCH + acol[i]) * 4u,
                 &A[(size_t)(bm + arow[i]) * K + k0 + acol[i]]);
#pragma unroll
        for (int i = 0; i < 2; ++i)
            cp16(bbase + (unsigned)(bkrow[i] * BPITCH + bncol[i]) * 4u,
                 &B[(size_t)(k0 + bkrow[i]) * N + bn + bncol[i]]);
    };

    float acc[2][4][4], mst[2][4][4];
#pragma unroll
    for (int mt = 0; mt < 2; ++mt)
#pragma unroll
        for (int nt = 0; nt < 4; ++nt)
#pragma unroll
            for (int r = 0; r < 4; ++r) { acc[mt][nt][r] = 0.f; mst[mt][nt][r] = 0.f; }

    // prologue: tiles 0,1,2 in flight
    issue_tile(0, 0);
    asm volatile("cp.async.commit_group;");
    if (ntiles > 1) issue_tile(1, 1);
    asm volatile("cp.async.commit_group;");
    if (ntiles > 2) issue_tile(2, 2);
    asm volatile("cp.async.commit_group;");

    for (int t = 0; t < ntiles; ++t) {
        asm volatile("cp.async.wait_group 2;");
        __syncthreads();

        if (t + 3 < ntiles) issue_tile(t + 3, (t + 3) % STAGES);
        asm volatile("cp.async.commit_group;");

        const float* Asf = smem_dyn + (t % STAGES) * STAGE_FLOATS;
        const float* Bsf = Asf + A_TILE_FLOATS;

#pragma unroll
        for (int ks = 0; ks < GBK / 8; ++ks) {
            int kb = ks * 8;
            unsigned ah[2][4], al[2][4];
#pragma unroll
            for (int mt = 0; mt < 2; ++mt) {
                int r0 = wm + mt * 16;
                tf32_split(Asf[(r0 + g) * SPITCH + kb + t4],         ah[mt][0], al[mt][0]);
                tf32_split(Asf[(r0 + g + 8) * SPITCH + kb + t4],     ah[mt][1], al[mt][1]);
                tf32_split(Asf[(r0 + g) * SPITCH + kb + t4 + 4],     ah[mt][2], al[mt][2]);
                tf32_split(Asf[(r0 + g + 8) * SPITCH + kb + t4 + 4], ah[mt][3], al[mt][3]);
            }
            unsigned bh[4][2], bl[4][2];
#pragma unroll
            for (int nt = 0; nt < 4; ++nt) {
                int col = wn + nt * 8 + g;
                tf32_split(Bsf[(kb + t4) * BPITCH + col],     bh[nt][0], bl[nt][0]);
                tf32_split(Bsf[(kb + t4 + 4) * BPITCH + col], bh[nt][1], bl[nt][1]);
            }
#pragma unroll
            for (int mt = 0; mt < 2; ++mt)
#pragma unroll
                for (int nt = 0; nt < 4; ++nt) {
                    mma_tf32(acc[mt][nt], ah[mt], bh[nt]);
                    mma_tf32(acc[mt][nt], al[mt], bh[nt]);
                    mma_tf32(acc[mt][nt], ah[mt], bl[nt]);
                }
        }

        if ((t & 3) == 3) {
#pragma unroll
            for (int mt = 0; mt < 2; ++mt)
#pragma unroll
                for (int nt = 0; nt < 4; ++nt)
#pragma unroll
                    for (int r = 0; r < 4; ++r) {
                        mst[mt][nt][r] = __fadd_rn(mst[mt][nt][r], acc[mt][nt][r]);
                        acc[mt][nt][r] = 0.f;
                    }
        }
    }

#pragma unroll
    for (int mt = 0; mt < 2; ++mt)
#pragma unroll
        for (int nt = 0; nt < 4; ++nt) {
            int r0 = bm + wm + mt * 16 + g;
            int c0 = bn + wn + nt * 8 + t4 * 2;
            *(float2*)&C[(size_t)r0 * N + c0] =
                make_float2(mst[mt][nt][0], mst[mt][nt][1]);
            *(float2*)&C[(size_t)(r0 + 8) * N + c0] =
                make_float2(mst[mt][nt][2], mst[mt][nt][3]);
        }
}

// ---------------- RoPE + layout transpose (precision-matched) ----------------
__global__ void rope_kernel()
{
    int p = blockIdx.x;
    int hh = blockIdx.y;
    int d = threadIdx.x;

    int i = d & 63;
    float P = (float)pow(10000.0, (double)(2 * i) / 128.0);
    float invf = __fdiv_rn(1.0f, P);
    float ang = __fmul_rn((float)p, invf);
    float c = (float)cos((double)ang);
    float s = (float)sin((double)ang);

    if (hh < NH) {
        const float* base = &g_qlin[(size_t)p * DMODEL + hh * HD];
        float v = base[d];
        float other = (d < 64) ? -base[d + 64] : base[d - 64];
        g_qr[((size_t)hh * QLEN + p) * HD + d] =
            __fadd_rn(__fmul_rn(v, c), __fmul_rn(other, s));
    } else if (hh < NH + NKV) {
        int kvh = hh - NH;
        const float* base = &g_klin[(size_t)p * (NKV * HD) + kvh * HD];
        float v = base[d];
        float other = (d < 64) ? -base[d + 64] : base[d - 64];
        g_kr[((size_t)kvh * QLEN + p) * HD + d] =
            __fadd_rn(__fmul_rn(v, c), __fmul_rn(other, s));
    } else {
        int kvh = hh - NH - NKV;
        g_vr[((size_t)kvh * QLEN + p) * HD + d] =
            g_vlin[(size_t)p * (NKV * HD) + kvh * HD + d];
    }
}

// ---------------- label build: 8 warps per block, one (p,h) per warp ------------
__global__ __launch_bounds__(256) void gqk_kernel(const int* __restrict__ sorted_channel)
{
    int warp = threadIdx.x >> 5;
    int lane = threadIdx.x & 31;
    int p = blockIdx.x;
    int h = blockIdx.y * 8 + warp;

    int j = lane & 15;
    bool isK = lane >= 16;

    int ch = sorted_channel[h * HD + j];
    float t;
    if (!isK) t = g_qr[((size_t)h * QLEN + p) * HD + ch];
    else      t = g_kr[((size_t)(h >> 2) * QLEN + p) * HD + ch];

    float mn = t, mx = t;
#pragma unroll
    for (int off = 1; off < 16; off <<= 1) {
        mn = fminf(mn, __shfl_xor_sync(0xffffffffu, mn, off));
        mx = fmaxf(mx, __shfl_xor_sync(0xffffffffu, mx, off));
    }
    float rng = __fadd_rn(mx, -mn);
    if (rng == 0.0f) rng = 1.0f;
    float scale = __fdiv_rn(15.0f, rng);
    float qv = rintf(__fmul_rn(__fadd_rn(t, -mn), scale));
    qv = fminf(fmaxf(qv, 0.0f), 15.0f);
    float outv = __fadd_rn(__fdiv_rn(qv, scale), mn);

    if (!isK) g_gq[((size_t)h * QLEN + p) * OUTL + j] = outv;
    else      g_gk[((size_t)h * QLEN + p) * OUTL + j] = outv;
}

// ---------------- fused gattn -> stable top-256 -> attn -> softmax -> AV --------
__global__ __launch_bounds__(256) void attn_kernel()
{
    int p = blockIdx.x;
    int h = blockIdx.y;
    int kvh = h >> 2;
    int tid = threadIdx.x;
    int lane = tid & 31;
    int warp = tid >> 5;
    unsigned lmask = (1u << lane) - 1u;

    __shared__ float gq_s[OUTL];
    __shared__ float q_s[HD];
    __shared__ unsigned hist[256];
    __shared__ unsigned wsum[8];
    __shared__ int kept_idx[KEEP];
    __shared__ float attw[KEEP];
    __shared__ float obuf[HD];
    __shared__ unsigned sh_prefix;
    __shared__ int sh_want;
    __shared__ int wcnt[8];
    __shared__ int wcnt2[8];
    __shared__ int eqbase_s;
    __shared__ int kbase_s;
    __shared__ float red[8];
    __shared__ float sh_scalar;

    if (tid < OUTL) gq_s[tid] = g_gq[((size_t)h * QLEN + p) * OUTL + tid];
    if (tid < HD)   q_s[tid] = g_qr[((size_t)h * QLEN + p) * HD + tid];
    if (tid == 0) { eqbase_s = 0; kbase_s = 0; }
    __syncthreads();

    int nvalid = p + 1;

    // 1. gattn keys -> registers (float4 loads, ascending FMA order)
    unsigned mykey[4];
#pragma unroll
    for (int chunk = 0; chunk < 4; ++chunk) {
        int j = chunk * 256 + tid;
        unsigned u = 0u;
        if (j < nvalid) {
            const float4* g4 = (const float4*)&g_gk[((size_t)h * QLEN + j) * OUTL];
            float4 a = g4[0], b = g4[1], c4 = g4[2], e = g4[3];
            float s = __fmul_rn(a.x, gq_s[0]);
            s = __fmaf_rn(a.y, gq_s[1], s);
            s = __fmaf_rn(a.z, gq_s[2], s);
            s = __fmaf_rn(a.w, gq_s[3], s);
            s = __fmaf_rn(b.x, gq_s[4], s);
            s = __fmaf_rn(b.y, gq_s[5], s);
            s = __fmaf_rn(b.z, gq_s[6], s);
            s = __fmaf_rn(b.w, gq_s[7], s);
            s = __fmaf_rn(c4.x, gq_s[8], s);
            s = __fmaf_rn(c4.y, gq_s[9], s);
            s = __fmaf_rn(c4.z, gq_s[10], s);
            s = __fmaf_rn(c4.w, gq_s[11], s);
            s = __fmaf_rn(e.x, gq_s[12], s);
            s = __fmaf_rn(e.y, gq_s[13], s);
            s = __fmaf_rn(e.z, gq_s[14], s);
            s = __fmaf_rn(e.w, gq_s[15], s);
            s = __fmul_rn(s, 0.25f);
            u = __float_as_uint(s);
            if ((u << 1) == 0u) u = 0u;
            u ^= (u & 0x80000000u) ? 0xFFFFFFFFu : 0x80000000u;
        }
        mykey[chunk] = u;
    }
    __syncthreads();

    // 2. stable top-KEEP selection (radix threshold + ordered compaction)
    int cnt;
    if (nvalid <= KEEP) {
        for (int j = tid; j < nvalid; j += 256) kept_idx[j] = j;
        cnt = nvalid;
        __syncthreads();
    } else {
        unsigned prefix = 0;
        int want = KEEP;
        for (int byte = 3; byte >= 0; --byte) {
            hist[tid] = 0;
            __syncthreads();
            int shift = byte * 8;
            unsigned pmask = (byte == 3) ? 0u : (0xFFFFFFFFu << (shift + 8));
#pragma unroll
            for (int chunk = 0; chunk < 4; ++chunk) {
                int j = chunk * 256 + tid;
                unsigned u = mykey[chunk];
                if (j < nvalid && (u & pmask) == prefix)
                    atomicAdd(&hist[(u >> shift) & 255u], 1u);
            }
            __syncthreads();

            unsigned hv = hist[tid];
            unsigned s = hv;
#pragma unroll
            for (int off = 1; off < 32; off <<= 1) {
                unsigned t2 = __shfl_down_sync(0xffffffffu, s, off);
                if (lane + off < 32) s += t2;
            }
            if (lane == 0) wsum[warp] = s;
            __syncthreads();
            unsigned add = 0;
#pragma unroll
            for (int w = 0; w < 8; ++w)
                if (w > warp) add += wsum[w];
            unsigned suft = s + add;
            unsigned above = suft - hv;
            if (suft >= (unsigned)want && above < (unsigned)want) {
                sh_prefix = prefix | ((unsigned)tid << shift);
                sh_want = want - (int)above;
            }
            __syncthreads();
            prefix = sh_prefix;
            want = sh_want;
            __syncthreads();
        }
        unsigned uT = prefix;
        int r = want;

        // ordered stable compaction: chunks asc, warps asc, lanes asc
#pragma unroll
        for (int chunk = 0; chunk < 4; ++chunk) {
            int j = chunk * 256 + tid;
            bool isval = j < nvalid;
            unsigned u = mykey[chunk];
            bool gt = isval && (u > uT);
            bool eq = isval && (u == uT);

            unsigned bal_eq = __ballot_sync(0xffffffffu, eq);
            if (lane == 0) wcnt[warp] = __popc(bal_eq);
            __syncthreads();
            int eqoff = eqbase_s;
            for (int w = 0; w < warp; ++w) eqoff += wcnt[w];
            int eqrank = eqoff + __popc(bal_eq & lmask);
            bool keep = gt || (eq && eqrank < r);

            unsigned bal_k = __ballot_sync(0xffffffffu, keep);
            if (lane == 0) wcnt2[warp] = __popc(bal_k);
            __syncthreads();
            int koff = kbase_s;
            for (int w = 0; w < warp; ++w) koff += wcnt2[w];
            if (keep) kept_idx[koff + __popc(bal_k & lmask)] = j;
            __syncthreads();
            if (tid == 0) {
                int te = 0, tk = 0;
                for (int w = 0; w < 8; ++w) { te += wcnt[w]; tk += wcnt2[w]; }
                eqbase_s += te;
                kbase_s += tk;
            }
            __syncthreads();
        }
        cnt = kbase_s;
    }
    __syncthreads();

    // 3. attn scores: warp per column, 2 columns in flight (same per-column math)
    {
        float4 qreg = *(const float4*)&q_s[lane * 4];
        const float* kbase = &g_kr[(size_t)kvh * QLEN * HD + lane * 4];
        for (int c = warp; c < cnt; c += 16) {
            int c1 = c + 8;
            int j0 = kept_idx[c];
            float4 kv0 = *(const float4*)&kbase[(size_t)j0 * HD];
            float4 kv1;
            int j1 = 0;
            bool has1 = c1 < cnt;
            if (has1) {
                j1 = kept_idx[c1];
                kv1 = *(const float4*)&kbase[(size_t)j1 * HD];
            }
            float s0 = __fmul_rn(qreg.x, kv0.x);
            s0 = __fmaf_rn(qreg.y, kv0.y, s0);
            s0 = __fmaf_rn(qreg.z, kv0.z, s0);
            s0 = __fmaf_rn(qreg.w, kv0.w, s0);
            float s1 = 0.f;
            if (has1) {
                s1 = __fmul_rn(qreg.x, kv1.x);
                s1 = __fmaf_rn(qreg.y, kv1.y, s1);
                s1 = __fmaf_rn(qreg.z, kv1.z, s1);
                s1 = __fmaf_rn(qreg.w, kv1.w, s1);
            }
#pragma unroll
            for (int off = 16; off; off >>= 1) {
                s0 += __shfl_xor_sync(0xffffffffu, s0, off);
                s1 += __shfl_xor_sync(0xffffffffu, s1, off);
            }
            if (lane == 0) {
                attw[c] = s0 / 11.313708498984761f;
                if (has1) attw[c1] = s1 / 11.313708498984761f;
            }
        }
    }
    __syncthreads();

    // 4. softmax over kept
    float vmax = -FLT_MAX;
    for (int c = tid; c < cnt; c += 256) vmax = fmaxf(vmax, attw[c]);
#pragma unroll
    for (int off = 16; off; off >>= 1)
        vmax = fmaxf(vmax, __shfl_xor_sync(0xffffffffu, vmax, off));
    if (lane == 0) red[warp] = vmax;
    __syncthreads();
    if (warp == 0) {
        float m = (lane < 8) ? red[lane] : -FLT_MAX;
#pragma unroll
        for (int off = 4; off; off >>= 1)
            m = fmaxf(m, __shfl_xor_sync(0xffffffffu, m, off));
        if (lane == 0) sh_scalar = m;
    }
    __syncthreads();
    float M = sh_scalar;

    float lsum = 0.f;
    for (int c = tid; c < cnt; c += 256) {
        float e = expf(__fadd_rn(attw[c], -M));
        attw[c] = e;
        lsum += e;
    }
#pragma unroll
    for (int off = 16; off; off >>= 1)
        lsum += __shfl_xor_sync(0xffffffffu, lsum, off);
    if (lane == 0) red[warp] = lsum;
    __syncthreads();
    if (warp == 0) {
        float s2 = (lane < 8) ? red[lane] : 0.f;
#pragma unroll
        for (int off = 4; off; off >>= 1)
            s2 += __shfl_xor_sync(0xffffffffu, s2, off);
        if (lane == 0) sh_scalar = s2;
    }
    __syncthreads();
    float denom = sh_scalar;

    for (int c = tid; c < cnt; c += 256)
        attw[c] = __fdiv_rn(attw[c], denom);
    __syncthreads();

    // 5. AV: two block-halves x two interleaved sub-accumulators (doubles MLP;
    //    summation-order change is post-selection ulp noise only)
    {
        int d = tid & 127;
        int half = tid >> 7;
        float acc0 = 0.f, acc1 = 0.f;
        const float* vbase = &g_vr[(size_t)kvh * QLEN * HD + d];
        int c0 = half, c1 = half + 2;
        for (; c1 < cnt; c0 += 4, c1 += 4) {
            acc0 = __fmaf_rn(attw[c0], __ldg(&vbase[(size_t)kept_idx[c0] * HD]), acc0);
            acc1 = __fmaf_rn(attw[c1], __ldg(&vbase[(size_t)kept_idx[c1] * HD]), acc1);
        }
        if (c0 < cnt)
            acc0 = __fmaf_rn(attw[c0], __ldg(&vbase[(size_t)kept_idx[c0] * HD]), acc0);
        float acc = __fadd_rn(acc0, acc1);
        if (half == 0) obuf[d] = acc;
        __syncthreads();
        if (half == 1)
            g_o[(size_t)p * (NH * HD) + h * HD + d] = __fadd_rn(obuf[d], acc);
    }
}

// ---------------- launch ----------------
extern "C" void kernel_launch(void* const* d_in, const int* in_sizes, int n_in,
                              void* d_out, int out_size)
{
    const float* hidden = (const float*)d_in[0];
    const float* Wq = (const float*)d_in[3];
    const float* Wk = (const float*)d_in[4];
    const float* Wv = (const float*)d_in[5];
    const float* Wo = (const float*)d_in[6];
    const int* sorted_channel = (const int*)d_in[7];
    float* out = (float*)d_out;

    float *qlin, *klin, *vlin, *o;
    cudaGetSymbolAddress((void**)&qlin, g_qlin);
    cudaGetSymbolAddress((void**)&klin, g_klin);
    cudaGetSymbolAddress((void**)&vlin, g_vlin);
    cudaGetSymbolAddress((void**)&o, g_o);

    cudaFuncSetAttribute(gemm_tf32,
                         cudaFuncAttributeMaxDynamicSharedMemorySize, SMEM_BYTES);

    dim3 t256(256);
    gemm_tf32<<<dim3(DMODEL / GBN, QLEN / GBM, 3), t256, SMEM_BYTES>>>(
        hidden,
        Wq, qlin, DMODEL,
        Wk, klin, NKV * HD,
        Wv, vlin, NKV * HD,
        DMODEL);
    rope_kernel<<<dim3(QLEN, NH + 2 * NKV), 128>>>();
    gqk_kernel<<<dim3(QLEN, NH / 8), t256>>>(sorted_channel);
    attn_kernel<<<dim3(QLEN, NH), t256>>>();
    gemm_tf32<<<dim3(DMODEL / GBN, QLEN / GBM, 1), t256, SMEM_BYTES>>>(
        o,
        Wo, out, DMODEL,
        Wo, out, DMODEL,
        Wo, out, DMODEL,
        DMODEL);
}